// round 12
// baseline (speedup 1.0000x reference)
#include <cuda_runtime.h>
#include <cuda_fp16.h>
#include <math.h>
#include <stdint.h>

// Problem constants
#define Bb 2
#define Nn 2048
#define Ww 1024
#define Hh 16
#define HDd 64
#define ROWS (Bb * Nn)   // 4096

// ----------------------------------------------------------------------------
// Scratch buffers
// ----------------------------------------------------------------------------
__device__ float g_x1[ROWS * Ww];            // post-attention residual (fp32)
__device__ __half g_ah[ROWS * Ww];           // ln output (fp16)
__device__ __half g_qh[ROWS * 3 * Ww];       // qkv (q pre-scaled), fp16
__device__ __half g_ath[ROWS * Ww];          // attention out (fp16)
__device__ __half g_hh[ROWS * 4 * Ww];       // gelu out (fp16)
// converted weights, [N,K] transposed fp16
__device__ __half g_w0[Ww * 3 * Ww];         // qkv_w^T
__device__ __half g_w1[Ww * Ww];             // proj_w^T
__device__ __half g_w2[Ww * 4 * Ww];         // fc_w^T
__device__ __half g_w3[4 * Ww * Ww];         // fc2_w^T

#define SWZ128(off) ((off) ^ (((off) >> 3) & 0x70))

__device__ __forceinline__ uint32_t smem_u32(const void* p) {
    uint32_t a;
    asm("{ .reg .u64 t; cvta.to.shared.u64 t, %1; cvt.u32.u64 %0, t; }" : "=r"(a) : "l"(p));
    return a;
}
__device__ __forceinline__ void cp16(uint32_t saddr, const void* g) {
    asm volatile("cp.async.cg.shared.global [%0], [%1], 16;" :: "r"(saddr), "l"(g));
}
#define CP_COMMIT() asm volatile("cp.async.commit_group;" ::: "memory")
#define CP_WAIT1()  asm volatile("cp.async.wait_group 1;" ::: "memory")
#define CP_WAIT0()  asm volatile("cp.async.wait_group 0;" ::: "memory")

__device__ __forceinline__ void ldsm_x4(uint32_t& a0, uint32_t& a1, uint32_t& a2, uint32_t& a3,
                                        uint32_t addr) {
    asm volatile("ldmatrix.sync.aligned.m8n8.x4.shared.b16 {%0,%1,%2,%3}, [%4];"
                 : "=r"(a0), "=r"(a1), "=r"(a2), "=r"(a3) : "r"(addr));
}
__device__ __forceinline__ void ldsm_x4t(uint32_t& a0, uint32_t& a1, uint32_t& a2, uint32_t& a3,
                                         uint32_t addr) {
    asm volatile("ldmatrix.sync.aligned.m8n8.x4.trans.shared.b16 {%0,%1,%2,%3}, [%4];"
                 : "=r"(a0), "=r"(a1), "=r"(a2), "=r"(a3) : "r"(addr));
}
__device__ __forceinline__ void mma_f16(float* c,
                                        uint32_t a0, uint32_t a1, uint32_t a2, uint32_t a3,
                                        uint32_t b0, uint32_t b1) {
    asm volatile(
        "mma.sync.aligned.m16n8k16.row.col.f32.f16.f16.f32 "
        "{%0,%1,%2,%3}, {%4,%5,%6,%7}, {%8,%9}, {%0,%1,%2,%3};"
        : "+f"(c[0]), "+f"(c[1]), "+f"(c[2]), "+f"(c[3])
        : "r"(a0), "r"(a1), "r"(a2), "r"(a3), "r"(b0), "r"(b1));
}
__device__ __forceinline__ uint32_t pack_h2(float a, float b) {
    __half2 t = __floats2half2_rn(a, b);
    return *(uint32_t*)&t;
}
__device__ __forceinline__ float gelu_exact(float v) {
    return 0.5f * v * (1.0f + erff(v * 0.70710678118654752f));
}

// ----------------------------------------------------------------------------
// convAll: convert+transpose all 4 weights in ONE launch.
// ----------------------------------------------------------------------------
__global__ void convAll_kernel(const float* __restrict__ w0, const float* __restrict__ w1,
                               const float* __restrict__ w2, const float* __restrict__ w3,
                               __half* __restrict__ d0, __half* __restrict__ d1,
                               __half* __restrict__ d2, __half* __restrict__ d3) {
    __shared__ float t[32][33];
    int id = blockIdx.x;
    const float* w; __half* d; int K, N;
    if (id < 3072)      { w = w0; d = d0; K = Ww;     N = 3 * Ww; }
    else if (id < 4096) { w = w1; d = d1; K = Ww;     N = Ww;     id -= 3072; }
    else if (id < 8192) { w = w2; d = d2; K = Ww;     N = 4 * Ww; id -= 4096; }
    else                { w = w3; d = d3; K = 4 * Ww; N = Ww;     id -= 8192; }
    int nx = N >> 5;
    int n0 = (id % nx) * 32, k0 = (id / nx) * 32;
    int tx = threadIdx.x, ty = threadIdx.y;   // 32 x 8
    #pragma unroll
    for (int i = 0; i < 32; i += 8)
        t[ty + i][tx] = w[(size_t)(k0 + ty + i) * N + n0 + tx];
    __syncthreads();
    #pragma unroll
    for (int i = 0; i < 32; i += 8)
        d[(size_t)(n0 + ty + i) * K + k0 + tx] = __float2half(t[tx][ty + i]);
}

// ----------------------------------------------------------------------------
// cp.async 3-stage mma.sync fp16 GEMM, single barrier per K chunk.
// CTA 128x128, K chunk 64, 8 warps (2x4), warp tile 64x32. 96 KB smem, 2 CTA/SM.
// EPI: 2 = bias+residual -> fp32; 3 = bias,q-scale -> fp16; 4 = bias+gelu -> fp16
// ----------------------------------------------------------------------------
#define GS_A 0
#define GS_B 16384
#define GS_STAGE 32768
#define GS_TOTAL (3 * GS_STAGE)   // 96 KB

template <int EPI>
__global__ void __launch_bounds__(256, 2)
tc_gemm(const __half* __restrict__ A, const __half* __restrict__ B,
        const float* __restrict__ bias, const float* __restrict__ res,
        float* __restrict__ Cf, __half* __restrict__ Ch,
        int M, int N, int K) {
    extern __shared__ char smem[];
    uint32_t sb = smem_u32(smem);
    const int tid = threadIdx.x, wid = tid >> 5, lid = tid & 31;
    const int bm = blockIdx.y * 128, bn = blockIdx.x * 128;
    const int wm = (wid & 1) * 64;
    const int wn = (wid >> 1) * 32;

    float acc[4][4][4];
    #pragma unroll
    for (int i = 0; i < 4; i++)
        #pragma unroll
        for (int j = 0; j < 4; j++)
            #pragma unroll
            for (int r = 0; r < 4; r++) acc[i][j][r] = 0.f;

    const int a_r  = lid & 15;
    const int a_kb = (lid >> 4) * 16;
    const int b_row = ((lid >> 4) & 1) * 8 + (lid & 7);
    const int b_kb  = ((lid >> 3) & 1) * 16;

    const int nchunk = K >> 6;
    #define G_LOAD(ck, s) do { \
        const int _k0 = (ck) << 6; \
        uint32_t _dst = sb + (s) * GS_STAGE; \
        _Pragma("unroll") \
        for (int _i = 0; _i < 4; _i++) { \
            int _idx = _i * 256 + tid; \
            int _r = _idx >> 3, _c = (_idx & 7) * 16; \
            uint32_t _so = SWZ128(_r * 128 + _c); \
            cp16(_dst + GS_A + _so, (const char*)(A + (size_t)(bm + _r) * K + _k0) + _c); \
            cp16(_dst + GS_B + _so, (const char*)(B + (size_t)(bn + _r) * K + _k0) + _c); \
        } \
        CP_COMMIT(); \
    } while (0)

    G_LOAD(0, 0);
    G_LOAD(1, 1);
    for (int ck = 0; ck < nchunk; ck++) {
        if (ck + 1 < nchunk) CP_WAIT1();
        else CP_WAIT0();
        __syncthreads();
        if (ck + 2 < nchunk) G_LOAD(ck + 2, (ck + 2) % 3);
        uint32_t stg = sb + (ck % 3) * GS_STAGE;
        #pragma unroll
        for (int ks = 0; ks < 4; ks++) {
            uint32_t a[4][4];
            #pragma unroll
            for (int i = 0; i < 4; i++) {
                uint32_t off = SWZ128((wm + i * 16 + a_r) * 128 + ks * 32 + a_kb);
                ldsm_x4(a[i][0], a[i][1], a[i][2], a[i][3], stg + GS_A + off);
            }
            #pragma unroll
            for (int jp = 0; jp < 2; jp++) {
                uint32_t b0, b1, b2, b3;
                uint32_t off = SWZ128((wn + jp * 16 + b_row) * 128 + ks * 32 + b_kb);
                ldsm_x4(b0, b1, b2, b3, stg + GS_B + off);
                #pragma unroll
                for (int i = 0; i < 4; i++) {
                    mma_f16(acc[i][2 * jp + 0], a[i][0], a[i][1], a[i][2], a[i][3], b0, b1);
                    mma_f16(acc[i][2 * jp + 1], a[i][0], a[i][1], a[i][2], a[i][3], b2, b3);
                }
            }
        }
    }
    #undef G_LOAD

    const int er = lid >> 2;
    const int ec = (lid & 3) * 2;
    #pragma unroll
    for (int i = 0; i < 4; i++) {
        #pragma unroll
        for (int j = 0; j < 4; j++) {
            int col = bn + wn + j * 8 + ec;
            float2 bi = *(const float2*)(bias + col);
            #pragma unroll
            for (int half = 0; half < 2; half++) {
                int row = bm + wm + i * 16 + er + half * 8;
                float ox = acc[i][j][half * 2 + 0] + bi.x;
                float oy = acc[i][j][half * 2 + 1] + bi.y;
                if (EPI == 2) {
                    float2 rv = *(const float2*)(res + (size_t)row * N + col);
                    float2 o = make_float2(ox + rv.x, oy + rv.y);
                    *(float2*)(Cf + (size_t)row * N + col) = o;
                } else {
                    if (EPI == 3) {
                        float s = ((col % 192) < 64) ? 0.125f : 1.0f;
                        ox *= s; oy *= s;
                    }
                    if (EPI == 4) { ox = gelu_exact(ox); oy = gelu_exact(oy); }
                    *(uint32_t*)(Ch + (size_t)row * N + col) = pack_h2(ox, oy);
                }
            }
        }
    }
}

// ----------------------------------------------------------------------------
// LayerNorm -> fp16, one warp per row (8 rows / 256-thread block)
// ----------------------------------------------------------------------------
__global__ void ln_kernel(const float* __restrict__ x, const float* __restrict__ g,
                          const float* __restrict__ beta, __half* __restrict__ yh) {
    int row = blockIdx.x * 8 + (threadIdx.x >> 5);
    int lane = threadIdx.x & 31;
    const float* xr = x + (size_t)row * Ww;
    float4 v[8];
    float s = 0.f, ss = 0.f;
    #pragma unroll
    for (int i = 0; i < 8; i++) {
        v[i] = *(const float4*)(xr + (i * 32 + lane) * 4);
        s  += v[i].x + v[i].y + v[i].z + v[i].w;
        ss += v[i].x * v[i].x + v[i].y * v[i].y + v[i].z * v[i].z + v[i].w * v[i].w;
    }
    #pragma unroll
    for (int off = 16; off; off >>= 1) {
        s  += __shfl_xor_sync(0xffffffffu, s, off);
        ss += __shfl_xor_sync(0xffffffffu, ss, off);
    }
    float mean = s * (1.f / Ww);
    float var  = ss * (1.f / Ww) - mean * mean;
    float rstd = rsqrtf(var + 1e-5f);
    #pragma unroll
    for (int i = 0; i < 8; i++) {
        int c4 = (i * 32 + lane) * 4;
        float4 gv = *(const float4*)(g + c4);
        float4 bv = *(const float4*)(beta + c4);
        float o0 = (v[i].x - mean) * rstd * gv.x + bv.x;
        float o1 = (v[i].y - mean) * rstd * gv.y + bv.y;
        float o2 = (v[i].z - mean) * rstd * gv.z + bv.z;
        float o3 = (v[i].w - mean) * rstd * gv.w + bv.w;
        uint2 o = make_uint2(pack_h2(o0, o1), pack_h2(o2, o3));
        *(uint2*)(yh + (size_t)row * Ww + c4) = o;
    }
}

// ----------------------------------------------------------------------------
// Tensor-core flash attention, fp16; h2exp softmax + deferred l reduction.
// ----------------------------------------------------------------------------
#define F_Q  0
#define F_ST 16384
#define F_K  0
#define F_V  8192
#define F_STAGE 16384
#define F_TOTAL (F_ST + 3 * F_STAGE)   // 64 KB

__global__ void __launch_bounds__(256, 2)
flash_tc(const __half* __restrict__ qh, __half* __restrict__ oh) {
    extern __shared__ char smem[];
    uint32_t sbm = smem_u32(smem);
    const int tid = threadIdx.x, wid = tid >> 5, lid = tid & 31;
    const int qt = blockIdx.x, h = blockIdx.y, b = blockIdx.z;
    const int wm = wid * 16;

    const size_t hcol = (size_t)h * 192;

    #pragma unroll
    for (int i = 0; i < 4; i++) {
        int idx = i * 256 + tid;
        int r = idx >> 3, c = (idx & 7) * 16;
        uint32_t so = SWZ128(r * 128 + c);
        const char* gq = (const char*)(qh + (size_t)(b * Nn + qt * 128 + r) * (3 * Ww) + hcol) + c;
        cp16(sbm + F_Q + so, gq);
    }
    CP_COMMIT();

    #define F_LOAD(kt, s) do { \
        uint32_t _dst = sbm + F_ST + (s) * F_STAGE; \
        _Pragma("unroll") \
        for (int _i = 0; _i < 2; _i++) { \
            int _idx = _i * 256 + tid; \
            int _r = _idx >> 3, _c = (_idx & 7) * 16; \
            uint32_t _so = SWZ128(_r * 128 + _c); \
            size_t _row = (size_t)(b * Nn + (kt) * 64 + _r) * (3 * Ww) + hcol; \
            cp16(_dst + F_K + _so, (const char*)(qh + _row + 64) + _c); \
            cp16(_dst + F_V + _so, (const char*)(qh + _row + 128) + _c); \
        } \
        CP_COMMIT(); \
    } while (0)

    F_LOAD(0, 0);
    F_LOAD(1, 1);

    const int a_r  = lid & 15;
    const int a_kb = (lid >> 4) * 16;
    const int k_row = ((lid >> 4) & 1) * 8 + (lid & 7);
    const int k_kb  = ((lid >> 3) & 1) * 16;
    const int v_row = ((lid >> 3) & 1) * 8 + (lid & 7);
    const int v_cb  = ((lid >> 4) & 1) * 16;

    float O[8][4];
    #pragma unroll
    for (int j = 0; j < 8; j++)
        #pragma unroll
        for (int r = 0; r < 4; r++) O[j][r] = 0.f;
    float m0 = -INFINITY, m1 = -INFINITY, l0 = 0.f, l1 = 0.f;

    const int NKT = Nn / 64;
    for (int kt = 0; kt < NKT; kt++) {
        if (kt + 1 < NKT) CP_WAIT1();
        else CP_WAIT0();
        __syncthreads();
        if (kt + 2 < NKT) F_LOAD(kt + 2, (kt + 2) % 3);
        uint32_t stg = sbm + F_ST + (kt % 3) * F_STAGE;

        float S[8][4];
        #pragma unroll
        for (int j = 0; j < 8; j++)
            #pragma unroll
            for (int r = 0; r < 4; r++) S[j][r] = 0.f;
        #pragma unroll
        for (int ks = 0; ks < 4; ks++) {
            uint32_t a0, a1, a2, a3;
            ldsm_x4(a0, a1, a2, a3, sbm + F_Q + SWZ128((wm + a_r) * 128 + ks * 32 + a_kb));
            #pragma unroll
            for (int jp = 0; jp < 4; jp++) {
                uint32_t b0, b1, b2, b3;
                uint32_t off = SWZ128((jp * 16 + k_row) * 128 + ks * 32 + k_kb);
                ldsm_x4(b0, b1, b2, b3, stg + F_K + off);
                mma_f16(S[2 * jp + 0], a0, a1, a2, a3, b0, b1);
                mma_f16(S[2 * jp + 1], a0, a1, a2, a3, b2, b3);
            }
        }

        // row max (needs full 64-col view: quad shuffle)
        float mx0 = -INFINITY, mx1 = -INFINITY;
        #pragma unroll
        for (int j = 0; j < 8; j++) {
            mx0 = fmaxf(mx0, fmaxf(S[j][0], S[j][1]));
            mx1 = fmaxf(mx1, fmaxf(S[j][2], S[j][3]));
        }
        mx0 = fmaxf(mx0, __shfl_xor_sync(0xffffffffu, mx0, 1));
        mx0 = fmaxf(mx0, __shfl_xor_sync(0xffffffffu, mx0, 2));
        mx1 = fmaxf(mx1, __shfl_xor_sync(0xffffffffu, mx1, 1));
        mx1 = fmaxf(mx1, __shfl_xor_sync(0xffffffffu, mx1, 2));
        float nm0 = fmaxf(m0, mx0), nm1 = fmaxf(m1, mx1);
        float al0 = __expf(m0 - nm0), al1 = __expf(m1 - nm1);
        m0 = nm0; m1 = nm1;

        // P = exp(S - m) via h2exp (2 values / MUFU op); l kept thread-local
        uint32_t P[8][2];
        float pl0 = 0.f, pl1 = 0.f;
        #pragma unroll
        for (int j = 0; j < 8; j++) {
            __half2 e0 = h2exp(__floats2half2_rn(S[j][0] - nm0, S[j][1] - nm0));
            __half2 e1 = h2exp(__floats2half2_rn(S[j][2] - nm1, S[j][3] - nm1));
            P[j][0] = *(uint32_t*)&e0;
            P[j][1] = *(uint32_t*)&e1;
            float2 f0 = __half22float2(e0);
            float2 f1 = __half22float2(e1);
            pl0 += f0.x + f0.y;
            pl1 += f1.x + f1.y;
        }
        l0 = l0 * al0 + pl0;
        l1 = l1 * al1 + pl1;

        if (!__all_sync(0xffffffffu, (al0 == 1.f) & (al1 == 1.f))) {
            #pragma unroll
            for (int j = 0; j < 8; j++) {
                O[j][0] *= al0; O[j][1] *= al0;
                O[j][2] *= al1; O[j][3] *= al1;
            }
        }

        #pragma unroll
        for (int t = 0; t < 4; t++) {
            uint32_t ph0 = P[2 * t][0], ph1 = P[2 * t][1];
            uint32_t ph2 = P[2 * t + 1][0], ph3 = P[2 * t + 1][1];
            #pragma unroll
            for (int jp = 0; jp < 4; jp++) {
                uint32_t v0, v1, v2, v3;
                uint32_t off = SWZ128((t * 16 + v_row) * 128 + jp * 32 + v_cb);
                ldsm_x4t(v0, v1, v2, v3, stg + F_V + off);
                mma_f16(O[2 * jp + 0], ph0, ph1, ph2, ph3, v0, v1);
                mma_f16(O[2 * jp + 1], ph0, ph1, ph2, ph3, v2, v3);
            }
        }
    }
    #undef F_LOAD

    // final l reduction across the quad (deferred from the mainloop)
    l0 += __shfl_xor_sync(0xffffffffu, l0, 1);
    l0 += __shfl_xor_sync(0xffffffffu, l0, 2);
    l1 += __shfl_xor_sync(0xffffffffu, l1, 1);
    l1 += __shfl_xor_sync(0xffffffffu, l1, 2);

    float inv0 = 1.f / l0, inv1 = 1.f / l1;
    int r0 = b * Nn + qt * 128 + wm + (lid >> 2);
    int r1 = r0 + 8;
    int cb = h * 64 + (lid & 3) * 2;
    #pragma unroll
    for (int j = 0; j < 8; j++) {
        int col = cb + j * 8;
        *(uint32_t*)(oh + (size_t)r0 * Ww + col) = pack_h2(O[j][0] * inv0, O[j][1] * inv0);
        *(uint32_t*)(oh + (size_t)r1 * Ww + col) = pack_h2(O[j][2] * inv1, O[j][3] * inv1);
    }
}

// ----------------------------------------------------------------------------
// Launcher
// ----------------------------------------------------------------------------
extern "C" void kernel_launch(void* const* d_in, const int* in_sizes, int n_in,
                              void* d_out, int out_size) {
    const float* x      = (const float*)d_in[0];
    const float* ln1_g  = (const float*)d_in[1];
    const float* ln1_b  = (const float*)d_in[2];
    const float* qkv_w  = (const float*)d_in[3];
    const float* qkv_b  = (const float*)d_in[4];
    const float* proj_w = (const float*)d_in[5];
    const float* proj_b = (const float*)d_in[6];
    const float* ln2_g  = (const float*)d_in[7];
    const float* ln2_b  = (const float*)d_in[8];
    const float* fc_w   = (const float*)d_in[9];
    const float* fc_b   = (const float*)d_in[10];
    const float* fc2_w  = (const float*)d_in[11];
    const float* fc2_b  = (const float*)d_in[12];
    float* out = (float*)d_out;

    float* x1;
    __half *ah, *qh, *ath, *hh, *w0, *w1, *w2, *w3;
    cudaGetSymbolAddress((void**)&x1,  g_x1);
    cudaGetSymbolAddress((void**)&ah,  g_ah);
    cudaGetSymbolAddress((void**)&qh,  g_qh);
    cudaGetSymbolAddress((void**)&ath, g_ath);
    cudaGetSymbolAddress((void**)&hh,  g_hh);
    cudaGetSymbolAddress((void**)&w0,  g_w0);
    cudaGetSymbolAddress((void**)&w1,  g_w1);
    cudaGetSymbolAddress((void**)&w2,  g_w2);
    cudaGetSymbolAddress((void**)&w3,  g_w3);

    cudaFuncSetAttribute(tc_gemm<2>, cudaFuncAttributeMaxDynamicSharedMemorySize, GS_TOTAL);
    cudaFuncSetAttribute(tc_gemm<3>, cudaFuncAttributeMaxDynamicSharedMemorySize, GS_TOTAL);
    cudaFuncSetAttribute(tc_gemm<4>, cudaFuncAttributeMaxDynamicSharedMemorySize, GS_TOTAL);
    cudaFuncSetAttribute(flash_tc, cudaFuncAttributeMaxDynamicSharedMemorySize, F_TOTAL);

    convAll_kernel<<<12288, dim3(32, 8)>>>(qkv_w, proj_w, fc_w, fc2_w, w0, w1, w2, w3);

    ln_kernel<<<ROWS / 8, 256>>>(x, ln1_g, ln1_b, ah);
    tc_gemm<3><<<dim3(3 * Ww / 128, ROWS / 128), 256, GS_TOTAL>>>(
        ah, w0, qkv_b, nullptr, nullptr, qh, ROWS, 3 * Ww, Ww);
    flash_tc<<<dim3(Nn / 128, Hh, Bb), 256, F_TOTAL>>>(qh, ath);
    tc_gemm<2><<<dim3(Ww / 128, ROWS / 128), 256, GS_TOTAL>>>(
        ath, w1, proj_b, x, x1, nullptr, ROWS, Ww, Ww);
    ln_kernel<<<ROWS / 8, 256>>>(x1, ln2_g, ln2_b, ah);
    tc_gemm<4><<<dim3(4 * Ww / 128, ROWS / 128), 256, GS_TOTAL>>>(
        ah, w2, fc_b, nullptr, nullptr, hh, ROWS, 4 * Ww, Ww);
    tc_gemm<2><<<dim3(Ww / 128, ROWS / 128), 256, GS_TOTAL>>>(
        hh, w3, fc2_b, x1, out, nullptr, ROWS, Ww, 4 * Ww);
}

// round 13
// speedup vs baseline: 1.0408x; 1.0408x over previous
#include <cuda_runtime.h>
#include <cuda_fp16.h>
#include <math.h>
#include <stdint.h>

// Problem constants
#define Bb 2
#define Nn 2048
#define Ww 1024
#define Hh 16
#define HDd 64
#define ROWS (Bb * Nn)   // 4096

// ----------------------------------------------------------------------------
// Scratch buffers
// ----------------------------------------------------------------------------
__device__ float g_x1[ROWS * Ww];            // post-attention residual (fp32)
__device__ __half g_ah[ROWS * Ww];           // ln output (fp16)
__device__ __half g_qh[ROWS * 3 * Ww];       // qkv (q pre-scaled by 0.125*log2e), fp16
__device__ __half g_ath[ROWS * Ww];          // attention out (fp16)
__device__ __half g_hh[ROWS * 4 * Ww];       // gelu out (fp16)
// converted weights, [N,K] transposed fp16
__device__ __half g_w0[Ww * 3 * Ww];         // qkv_w^T
__device__ __half g_w1[Ww * Ww];             // proj_w^T
__device__ __half g_w2[Ww * 4 * Ww];         // fc_w^T
__device__ __half g_w3[4 * Ww * Ww];         // fc2_w^T

#define SWZ128(off) ((off) ^ (((off) >> 3) & 0x70))

__device__ __forceinline__ uint32_t smem_u32(const void* p) {
    uint32_t a;
    asm("{ .reg .u64 t; cvta.to.shared.u64 t, %1; cvt.u32.u64 %0, t; }" : "=r"(a) : "l"(p));
    return a;
}
__device__ __forceinline__ void cp16(uint32_t saddr, const void* g) {
    asm volatile("cp.async.cg.shared.global [%0], [%1], 16;" :: "r"(saddr), "l"(g));
}
#define CP_COMMIT() asm volatile("cp.async.commit_group;" ::: "memory")
#define CP_WAIT1()  asm volatile("cp.async.wait_group 1;" ::: "memory")
#define CP_WAIT0()  asm volatile("cp.async.wait_group 0;" ::: "memory")

__device__ __forceinline__ void ldsm_x4(uint32_t& a0, uint32_t& a1, uint32_t& a2, uint32_t& a3,
                                        uint32_t addr) {
    asm volatile("ldmatrix.sync.aligned.m8n8.x4.shared.b16 {%0,%1,%2,%3}, [%4];"
                 : "=r"(a0), "=r"(a1), "=r"(a2), "=r"(a3) : "r"(addr));
}
__device__ __forceinline__ void ldsm_x4t(uint32_t& a0, uint32_t& a1, uint32_t& a2, uint32_t& a3,
                                         uint32_t addr) {
    asm volatile("ldmatrix.sync.aligned.m8n8.x4.trans.shared.b16 {%0,%1,%2,%3}, [%4];"
                 : "=r"(a0), "=r"(a1), "=r"(a2), "=r"(a3) : "r"(addr));
}
__device__ __forceinline__ void mma_f16(float* c,
                                        uint32_t a0, uint32_t a1, uint32_t a2, uint32_t a3,
                                        uint32_t b0, uint32_t b1) {
    asm volatile(
        "mma.sync.aligned.m16n8k16.row.col.f32.f16.f16.f32 "
        "{%0,%1,%2,%3}, {%4,%5,%6,%7}, {%8,%9}, {%0,%1,%2,%3};"
        : "+f"(c[0]), "+f"(c[1]), "+f"(c[2]), "+f"(c[3])
        : "r"(a0), "r"(a1), "r"(a2), "r"(a3), "r"(b0), "r"(b1));
}
__device__ __forceinline__ uint32_t pack_h2(float a, float b) {
    __half2 t = __floats2half2_rn(a, b);
    return *(uint32_t*)&t;
}
__device__ __forceinline__ float gelu_exact(float v) {
    return 0.5f * v * (1.0f + erff(v * 0.70710678118654752f));
}

// ----------------------------------------------------------------------------
// convAll: convert+transpose all 4 weights in ONE launch.
// ----------------------------------------------------------------------------
__global__ void convAll_kernel(const float* __restrict__ w0, const float* __restrict__ w1,
                               const float* __restrict__ w2, const float* __restrict__ w3,
                               __half* __restrict__ d0, __half* __restrict__ d1,
                               __half* __restrict__ d2, __half* __restrict__ d3) {
    __shared__ float t[32][33];
    int id = blockIdx.x;
    const float* w; __half* d; int K, N;
    if (id < 3072)      { w = w0; d = d0; K = Ww;     N = 3 * Ww; }
    else if (id < 4096) { w = w1; d = d1; K = Ww;     N = Ww;     id -= 3072; }
    else if (id < 8192) { w = w2; d = d2; K = Ww;     N = 4 * Ww; id -= 4096; }
    else                { w = w3; d = d3; K = 4 * Ww; N = Ww;     id -= 8192; }
    int nx = N >> 5;
    int n0 = (id % nx) * 32, k0 = (id / nx) * 32;
    int tx = threadIdx.x, ty = threadIdx.y;   // 32 x 8
    #pragma unroll
    for (int i = 0; i < 32; i += 8)
        t[ty + i][tx] = w[(size_t)(k0 + ty + i) * N + n0 + tx];
    __syncthreads();
    #pragma unroll
    for (int i = 0; i < 32; i += 8)
        d[(size_t)(n0 + ty + i) * K + k0 + tx] = __float2half(t[tx][ty + i]);
}

// ----------------------------------------------------------------------------
// cp.async 3-stage mma.sync fp16 GEMM, single barrier per K chunk.
// CTA 128x128, K chunk 64, 8 warps (2x4), warp tile 64x32. 96 KB smem, 2 CTA/SM.
// EPI: 2 = bias+residual -> fp32; 3 = bias,q-scale(log2 domain) -> fp16;
//      4 = bias+gelu -> fp16
// ----------------------------------------------------------------------------
#define GS_A 0
#define GS_B 16384
#define GS_STAGE 32768
#define GS_TOTAL (3 * GS_STAGE)   // 96 KB

template <int EPI>
__global__ void __launch_bounds__(256, 2)
tc_gemm(const __half* __restrict__ A, const __half* __restrict__ B,
        const float* __restrict__ bias, const float* __restrict__ res,
        float* __restrict__ Cf, __half* __restrict__ Ch,
        int M, int N, int K) {
    extern __shared__ char smem[];
    uint32_t sb = smem_u32(smem);
    const int tid = threadIdx.x, wid = tid >> 5, lid = tid & 31;
    const int bm = blockIdx.y * 128, bn = blockIdx.x * 128;
    const int wm = (wid & 1) * 64;
    const int wn = (wid >> 1) * 32;

    float acc[4][4][4];
    #pragma unroll
    for (int i = 0; i < 4; i++)
        #pragma unroll
        for (int j = 0; j < 4; j++)
            #pragma unroll
            for (int r = 0; r < 4; r++) acc[i][j][r] = 0.f;

    const int a_r  = lid & 15;
    const int a_kb = (lid >> 4) * 16;
    const int b_row = ((lid >> 4) & 1) * 8 + (lid & 7);
    const int b_kb  = ((lid >> 3) & 1) * 16;

    const int nchunk = K >> 6;
    #define G_LOAD(ck, s) do { \
        const int _k0 = (ck) << 6; \
        uint32_t _dst = sb + (s) * GS_STAGE; \
        _Pragma("unroll") \
        for (int _i = 0; _i < 4; _i++) { \
            int _idx = _i * 256 + tid; \
            int _r = _idx >> 3, _c = (_idx & 7) * 16; \
            uint32_t _so = SWZ128(_r * 128 + _c); \
            cp16(_dst + GS_A + _so, (const char*)(A + (size_t)(bm + _r) * K + _k0) + _c); \
            cp16(_dst + GS_B + _so, (const char*)(B + (size_t)(bn + _r) * K + _k0) + _c); \
        } \
        CP_COMMIT(); \
    } while (0)

    G_LOAD(0, 0);
    G_LOAD(1, 1);
    for (int ck = 0; ck < nchunk; ck++) {
        if (ck + 1 < nchunk) CP_WAIT1();
        else CP_WAIT0();
        __syncthreads();
        if (ck + 2 < nchunk) G_LOAD(ck + 2, (ck + 2) % 3);
        uint32_t stg = sb + (ck % 3) * GS_STAGE;
        #pragma unroll
        for (int ks = 0; ks < 4; ks++) {
            uint32_t a[4][4];
            #pragma unroll
            for (int i = 0; i < 4; i++) {
                uint32_t off = SWZ128((wm + i * 16 + a_r) * 128 + ks * 32 + a_kb);
                ldsm_x4(a[i][0], a[i][1], a[i][2], a[i][3], stg + GS_A + off);
            }
            #pragma unroll
            for (int jp = 0; jp < 2; jp++) {
                uint32_t b0, b1, b2, b3;
                uint32_t off = SWZ128((wn + jp * 16 + b_row) * 128 + ks * 32 + b_kb);
                ldsm_x4(b0, b1, b2, b3, stg + GS_B + off);
                #pragma unroll
                for (int i = 0; i < 4; i++) {
                    mma_f16(acc[i][2 * jp + 0], a[i][0], a[i][1], a[i][2], a[i][3], b0, b1);
                    mma_f16(acc[i][2 * jp + 1], a[i][0], a[i][1], a[i][2], a[i][3], b2, b3);
                }
            }
        }
    }
    #undef G_LOAD

    const int er = lid >> 2;
    const int ec = (lid & 3) * 2;
    #pragma unroll
    for (int i = 0; i < 4; i++) {
        #pragma unroll
        for (int j = 0; j < 4; j++) {
            int col = bn + wn + j * 8 + ec;
            float2 bi = *(const float2*)(bias + col);
            #pragma unroll
            for (int half = 0; half < 2; half++) {
                int row = bm + wm + i * 16 + er + half * 8;
                float ox = acc[i][j][half * 2 + 0] + bi.x;
                float oy = acc[i][j][half * 2 + 1] + bi.y;
                if (EPI == 2) {
                    float2 rv = *(const float2*)(res + (size_t)row * N + col);
                    float2 o = make_float2(ox + rv.x, oy + rv.y);
                    *(float2*)(Cf + (size_t)row * N + col) = o;
                } else {
                    if (EPI == 3) {
                        // q gets 0.125 (both sqrt-scales) * log2(e) so softmax can use exp2
                        float s = ((col % 192) < 64) ? 0.18033688f : 1.0f;
                        ox *= s; oy *= s;
                    }
                    if (EPI == 4) { ox = gelu_exact(ox); oy = gelu_exact(oy); }
                    *(uint32_t*)(Ch + (size_t)row * N + col) = pack_h2(ox, oy);
                }
            }
        }
    }
}

// ----------------------------------------------------------------------------
// LayerNorm -> fp16, one warp per row (8 rows / 256-thread block)
// ----------------------------------------------------------------------------
__global__ void ln_kernel(const float* __restrict__ x, const float* __restrict__ g,
                          const float* __restrict__ beta, __half* __restrict__ yh) {
    int row = blockIdx.x * 8 + (threadIdx.x >> 5);
    int lane = threadIdx.x & 31;
    const float* xr = x + (size_t)row * Ww;
    float4 v[8];
    float s = 0.f, ss = 0.f;
    #pragma unroll
    for (int i = 0; i < 8; i++) {
        v[i] = *(const float4*)(xr + (i * 32 + lane) * 4);
        s  += v[i].x + v[i].y + v[i].z + v[i].w;
        ss += v[i].x * v[i].x + v[i].y * v[i].y + v[i].z * v[i].z + v[i].w * v[i].w;
    }
    #pragma unroll
    for (int off = 16; off; off >>= 1) {
        s  += __shfl_xor_sync(0xffffffffu, s, off);
        ss += __shfl_xor_sync(0xffffffffu, ss, off);
    }
    float mean = s * (1.f / Ww);
    float var  = ss * (1.f / Ww) - mean * mean;
    float rstd = rsqrtf(var + 1e-5f);
    #pragma unroll
    for (int i = 0; i < 8; i++) {
        int c4 = (i * 32 + lane) * 4;
        float4 gv = *(const float4*)(g + c4);
        float4 bv = *(const float4*)(beta + c4);
        float o0 = (v[i].x - mean) * rstd * gv.x + bv.x;
        float o1 = (v[i].y - mean) * rstd * gv.y + bv.y;
        float o2 = (v[i].z - mean) * rstd * gv.z + bv.z;
        float o3 = (v[i].w - mean) * rstd * gv.w + bv.w;
        uint2 o = make_uint2(pack_h2(o0, o1), pack_h2(o2, o3));
        *(uint2*)(yh + (size_t)row * Ww + c4) = o;
    }
}

// ----------------------------------------------------------------------------
// Tensor-core flash attention, fp16; exp2 softmax (log2-domain scores),
// deferred l reduction.
// ----------------------------------------------------------------------------
#define F_Q  0
#define F_ST 16384
#define F_K  0
#define F_V  8192
#define F_STAGE 16384
#define F_TOTAL (F_ST + 3 * F_STAGE)   // 64 KB

__global__ void __launch_bounds__(256, 2)
flash_tc(const __half* __restrict__ qh, __half* __restrict__ oh) {
    extern __shared__ char smem[];
    uint32_t sbm = smem_u32(smem);
    const int tid = threadIdx.x, wid = tid >> 5, lid = tid & 31;
    const int qt = blockIdx.x, h = blockIdx.y, b = blockIdx.z;
    const int wm = wid * 16;

    const size_t hcol = (size_t)h * 192;

    #pragma unroll
    for (int i = 0; i < 4; i++) {
        int idx = i * 256 + tid;
        int r = idx >> 3, c = (idx & 7) * 16;
        uint32_t so = SWZ128(r * 128 + c);
        const char* gq = (const char*)(qh + (size_t)(b * Nn + qt * 128 + r) * (3 * Ww) + hcol) + c;
        cp16(sbm + F_Q + so, gq);
    }
    CP_COMMIT();

    #define F_LOAD(kt, s) do { \
        uint32_t _dst = sbm + F_ST + (s) * F_STAGE; \
        _Pragma("unroll") \
        for (int _i = 0; _i < 2; _i++) { \
            int _idx = _i * 256 + tid; \
            int _r = _idx >> 3, _c = (_idx & 7) * 16; \
            uint32_t _so = SWZ128(_r * 128 + _c); \
            size_t _row = (size_t)(b * Nn + (kt) * 64 + _r) * (3 * Ww) + hcol; \
            cp16(_dst + F_K + _so, (const char*)(qh + _row + 64) + _c); \
            cp16(_dst + F_V + _so, (const char*)(qh + _row + 128) + _c); \
        } \
        CP_COMMIT(); \
    } while (0)

    F_LOAD(0, 0);
    F_LOAD(1, 1);

    const int a_r  = lid & 15;
    const int a_kb = (lid >> 4) * 16;
    const int k_row = ((lid >> 4) & 1) * 8 + (lid & 7);
    const int k_kb  = ((lid >> 3) & 1) * 16;
    const int v_row = ((lid >> 3) & 1) * 8 + (lid & 7);
    const int v_cb  = ((lid >> 4) & 1) * 16;

    float O[8][4];
    #pragma unroll
    for (int j = 0; j < 8; j++)
        #pragma unroll
        for (int r = 0; r < 4; r++) O[j][r] = 0.f;
    float m0 = -INFINITY, m1 = -INFINITY, l0 = 0.f, l1 = 0.f;

    const int NKT = Nn / 64;
    for (int kt = 0; kt < NKT; kt++) {
        if (kt + 1 < NKT) CP_WAIT1();
        else CP_WAIT0();
        __syncthreads();
        if (kt + 2 < NKT) F_LOAD(kt + 2, (kt + 2) % 3);
        uint32_t stg = sbm + F_ST + (kt % 3) * F_STAGE;

        float S[8][4];
        #pragma unroll
        for (int j = 0; j < 8; j++)
            #pragma unroll
            for (int r = 0; r < 4; r++) S[j][r] = 0.f;
        #pragma unroll
        for (int ks = 0; ks < 4; ks++) {
            uint32_t a0, a1, a2, a3;
            ldsm_x4(a0, a1, a2, a3, sbm + F_Q + SWZ128((wm + a_r) * 128 + ks * 32 + a_kb));
            #pragma unroll
            for (int jp = 0; jp < 4; jp++) {
                uint32_t b0, b1, b2, b3;
                uint32_t off = SWZ128((jp * 16 + k_row) * 128 + ks * 32 + k_kb);
                ldsm_x4(b0, b1, b2, b3, stg + F_K + off);
                mma_f16(S[2 * jp + 0], a0, a1, a2, a3, b0, b1);
                mma_f16(S[2 * jp + 1], a0, a1, a2, a3, b2, b3);
            }
        }

        // row max (log2-domain scores)
        float mx0 = -INFINITY, mx1 = -INFINITY;
        #pragma unroll
        for (int j = 0; j < 8; j++) {
            mx0 = fmaxf(mx0, fmaxf(S[j][0], S[j][1]));
            mx1 = fmaxf(mx1, fmaxf(S[j][2], S[j][3]));
        }
        mx0 = fmaxf(mx0, __shfl_xor_sync(0xffffffffu, mx0, 1));
        mx0 = fmaxf(mx0, __shfl_xor_sync(0xffffffffu, mx0, 2));
        mx1 = fmaxf(mx1, __shfl_xor_sync(0xffffffffu, mx1, 1));
        mx1 = fmaxf(mx1, __shfl_xor_sync(0xffffffffu, mx1, 2));
        float nm0 = fmaxf(m0, mx0), nm1 = fmaxf(m1, mx1);
        float al0 = exp2f(m0 - nm0), al1 = exp2f(m1 - nm1);
        m0 = nm0; m1 = nm1;

        // P = 2^(S - m); l kept thread-local (deferred quad reduction)
        uint32_t P[8][2];
        float pl0 = 0.f, pl1 = 0.f;
        #pragma unroll
        for (int j = 0; j < 8; j++) {
            float e0 = exp2f(S[j][0] - nm0);
            float e1 = exp2f(S[j][1] - nm0);
            float e2 = exp2f(S[j][2] - nm1);
            float e3 = exp2f(S[j][3] - nm1);
            pl0 += e0 + e1;
            pl1 += e2 + e3;
            P[j][0] = pack_h2(e0, e1);
            P[j][1] = pack_h2(e2, e3);
        }
        l0 = l0 * al0 + pl0;
        l1 = l1 * al1 + pl1;

        if (!__all_sync(0xffffffffu, (al0 == 1.f) & (al1 == 1.f))) {
            #pragma unroll
            for (int j = 0; j < 8; j++) {
                O[j][0] *= al0; O[j][1] *= al0;
                O[j][2] *= al1; O[j][3] *= al1;
            }
        }

        #pragma unroll
        for (int t = 0; t < 4; t++) {
            uint32_t ph0 = P[2 * t][0], ph1 = P[2 * t][1];
            uint32_t ph2 = P[2 * t + 1][0], ph3 = P[2 * t + 1][1];
            #pragma unroll
            for (int jp = 0; jp < 4; jp++) {
                uint32_t v0, v1, v2, v3;
                uint32_t off = SWZ128((t * 16 + v_row) * 128 + jp * 32 + v_cb);
                ldsm_x4t(v0, v1, v2, v3, stg + F_V + off);
                mma_f16(O[2 * jp + 0], ph0, ph1, ph2, ph3, v0, v1);
                mma_f16(O[2 * jp + 1], ph0, ph1, ph2, ph3, v2, v3);
            }
        }
    }
    #undef F_LOAD

    // final l reduction across the quad
    l0 += __shfl_xor_sync(0xffffffffu, l0, 1);
    l0 += __shfl_xor_sync(0xffffffffu, l0, 2);
    l1 += __shfl_xor_sync(0xffffffffu, l1, 1);
    l1 += __shfl_xor_sync(0xffffffffu, l1, 2);

    float inv0 = 1.f / l0, inv1 = 1.f / l1;
    int r0 = b * Nn + qt * 128 + wm + (lid >> 2);
    int r1 = r0 + 8;
    int cb = h * 64 + (lid & 3) * 2;
    #pragma unroll
    for (int j = 0; j < 8; j++) {
        int col = cb + j * 8;
        *(uint32_t*)(oh + (size_t)r0 * Ww + col) = pack_h2(O[j][0] * inv0, O[j][1] * inv0);
        *(uint32_t*)(oh + (size_t)r1 * Ww + col) = pack_h2(O[j][2] * inv1, O[j][3] * inv1);
    }
}

// ----------------------------------------------------------------------------
// Launcher
// ----------------------------------------------------------------------------
extern "C" void kernel_launch(void* const* d_in, const int* in_sizes, int n_in,
                              void* d_out, int out_size) {
    const float* x      = (const float*)d_in[0];
    const float* ln1_g  = (const float*)d_in[1];
    const float* ln1_b  = (const float*)d_in[2];
    const float* qkv_w  = (const float*)d_in[3];
    const float* qkv_b  = (const float*)d_in[4];
    const float* proj_w = (const float*)d_in[5];
    const float* proj_b = (const float*)d_in[6];
    const float* ln2_g  = (const float*)d_in[7];
    const float* ln2_b  = (const float*)d_in[8];
    const float* fc_w   = (const float*)d_in[9];
    const float* fc_b   = (const float*)d_in[10];
    const float* fc2_w  = (const float*)d_in[11];
    const float* fc2_b  = (const float*)d_in[12];
    float* out = (float*)d_out;

    float* x1;
    __half *ah, *qh, *ath, *hh, *w0, *w1, *w2, *w3;
    cudaGetSymbolAddress((void**)&x1,  g_x1);
    cudaGetSymbolAddress((void**)&ah,  g_ah);
    cudaGetSymbolAddress((void**)&qh,  g_qh);
    cudaGetSymbolAddress((void**)&ath, g_ath);
    cudaGetSymbolAddress((void**)&hh,  g_hh);
    cudaGetSymbolAddress((void**)&w0,  g_w0);
    cudaGetSymbolAddress((void**)&w1,  g_w1);
    cudaGetSymbolAddress((void**)&w2,  g_w2);
    cudaGetSymbolAddress((void**)&w3,  g_w3);

    cudaFuncSetAttribute(tc_gemm<2>, cudaFuncAttributeMaxDynamicSharedMemorySize, GS_TOTAL);
    cudaFuncSetAttribute(tc_gemm<3>, cudaFuncAttributeMaxDynamicSharedMemorySize, GS_TOTAL);
    cudaFuncSetAttribute(tc_gemm<4>, cudaFuncAttributeMaxDynamicSharedMemorySize, GS_TOTAL);
    cudaFuncSetAttribute(flash_tc, cudaFuncAttributeMaxDynamicSharedMemorySize, F_TOTAL);

    convAll_kernel<<<12288, dim3(32, 8)>>>(qkv_w, proj_w, fc_w, fc2_w, w0, w1, w2, w3);

    ln_kernel<<<ROWS / 8, 256>>>(x, ln1_g, ln1_b, ah);
    tc_gemm<3><<<dim3(3 * Ww / 128, ROWS / 128), 256, GS_TOTAL>>>(
        ah, w0, qkv_b, nullptr, nullptr, qh, ROWS, 3 * Ww, Ww);
    flash_tc<<<dim3(Nn / 128, Hh, Bb), 256, F_TOTAL>>>(qh, ath);
    tc_gemm<2><<<dim3(Ww / 128, ROWS / 128), 256, GS_TOTAL>>>(
        ath, w1, proj_b, x, x1, nullptr, ROWS, Ww, Ww);
    ln_kernel<<<ROWS / 8, 256>>>(x1, ln2_g, ln2_b, ah);
    tc_gemm<4><<<dim3(4 * Ww / 128, ROWS / 128), 256, GS_TOTAL>>>(
        ah, w2, fc_b, nullptr, nullptr, hh, ROWS, 4 * Ww, Ww);
    tc_gemm<2><<<dim3(Ww / 128, ROWS / 128), 256, GS_TOTAL>>>(
        hh, w3, fc2_b, x1, out, nullptr, ROWS, Ww, 4 * Ww);
}

// round 14
// speedup vs baseline: 1.0540x; 1.0127x over previous
#include <cuda_runtime.h>
#include <cuda_fp16.h>
#include <math.h>
#include <stdint.h>

// Problem constants
#define Bb 2
#define Nn 2048
#define Ww 1024
#define Hh 16
#define HDd 64
#define ROWS (Bb * Nn)   // 4096

// ----------------------------------------------------------------------------
// Scratch buffers
// ----------------------------------------------------------------------------
__device__ float g_x1[ROWS * Ww];            // post-attention residual (fp32)
__device__ __half g_ah[ROWS * Ww];           // ln output (fp16)
__device__ __half g_qh[ROWS * 3 * Ww];       // qkv (q pre-scaled by 0.125*log2e), fp16
__device__ __half g_ath[ROWS * Ww];          // attention out (fp16)
__device__ __half g_hh[ROWS * 4 * Ww];       // gelu out (fp16)
// converted weights, [N,K] transposed fp16
__device__ __half g_w0[Ww * 3 * Ww];         // qkv_w^T
__device__ __half g_w1[Ww * Ww];             // proj_w^T
__device__ __half g_w2[Ww * 4 * Ww];         // fc_w^T
__device__ __half g_w3[4 * Ww * Ww];         // fc2_w^T

#define SWZ128(off) ((off) ^ (((off) >> 3) & 0x70))

__device__ __forceinline__ uint32_t smem_u32(const void* p) {
    uint32_t a;
    asm("{ .reg .u64 t; cvta.to.shared.u64 t, %1; cvt.u32.u64 %0, t; }" : "=r"(a) : "l"(p));
    return a;
}
__device__ __forceinline__ void cp16(uint32_t saddr, const void* g) {
    asm volatile("cp.async.cg.shared.global [%0], [%1], 16;" :: "r"(saddr), "l"(g));
}
#define CP_COMMIT() asm volatile("cp.async.commit_group;" ::: "memory")
#define CP_WAIT1()  asm volatile("cp.async.wait_group 1;" ::: "memory")
#define CP_WAIT0()  asm volatile("cp.async.wait_group 0;" ::: "memory")

__device__ __forceinline__ void ldsm_x4(uint32_t& a0, uint32_t& a1, uint32_t& a2, uint32_t& a3,
                                        uint32_t addr) {
    asm volatile("ldmatrix.sync.aligned.m8n8.x4.shared.b16 {%0,%1,%2,%3}, [%4];"
                 : "=r"(a0), "=r"(a1), "=r"(a2), "=r"(a3) : "r"(addr));
}
__device__ __forceinline__ void ldsm_x4t(uint32_t& a0, uint32_t& a1, uint32_t& a2, uint32_t& a3,
                                         uint32_t addr) {
    asm volatile("ldmatrix.sync.aligned.m8n8.x4.trans.shared.b16 {%0,%1,%2,%3}, [%4];"
                 : "=r"(a0), "=r"(a1), "=r"(a2), "=r"(a3) : "r"(addr));
}
__device__ __forceinline__ void mma_f16(float* c,
                                        uint32_t a0, uint32_t a1, uint32_t a2, uint32_t a3,
                                        uint32_t b0, uint32_t b1) {
    asm volatile(
        "mma.sync.aligned.m16n8k16.row.col.f32.f16.f16.f32 "
        "{%0,%1,%2,%3}, {%4,%5,%6,%7}, {%8,%9}, {%0,%1,%2,%3};"
        : "+f"(c[0]), "+f"(c[1]), "+f"(c[2]), "+f"(c[3])
        : "r"(a0), "r"(a1), "r"(a2), "r"(a3), "r"(b0), "r"(b1));
}
__device__ __forceinline__ uint32_t pack_h2(float a, float b) {
    __half2 t = __floats2half2_rn(a, b);
    return *(uint32_t*)&t;
}
// tanh-form GELU via single EX2 + fast reciprocal:
// gelu(x) ~= x * z / (z + 1), z = 2^(2.302118*(x + 0.044715 x^3))
__device__ __forceinline__ float gelu_fast(float x) {
    float x2 = x * x;
    float u = fmaf(0.044715f * x2, x, x);       // x + 0.044715 x^3
    float z = exp2f(2.3021183f * u);
    return x * __fdividef(z, z + 1.0f);
}

// ----------------------------------------------------------------------------
// convAll: convert+transpose all 4 weights in ONE launch.
// ----------------------------------------------------------------------------
__global__ void convAll_kernel(const float* __restrict__ w0, const float* __restrict__ w1,
                               const float* __restrict__ w2, const float* __restrict__ w3,
                               __half* __restrict__ d0, __half* __restrict__ d1,
                               __half* __restrict__ d2, __half* __restrict__ d3) {
    __shared__ float t[32][33];
    int id = blockIdx.x;
    const float* w; __half* d; int K, N;
    if (id < 3072)      { w = w0; d = d0; K = Ww;     N = 3 * Ww; }
    else if (id < 4096) { w = w1; d = d1; K = Ww;     N = Ww;     id -= 3072; }
    else if (id < 8192) { w = w2; d = d2; K = Ww;     N = 4 * Ww; id -= 4096; }
    else                { w = w3; d = d3; K = 4 * Ww; N = Ww;     id -= 8192; }
    int nx = N >> 5;
    int n0 = (id % nx) * 32, k0 = (id / nx) * 32;
    int tx = threadIdx.x, ty = threadIdx.y;   // 32 x 8
    #pragma unroll
    for (int i = 0; i < 32; i += 8)
        t[ty + i][tx] = w[(size_t)(k0 + ty + i) * N + n0 + tx];
    __syncthreads();
    #pragma unroll
    for (int i = 0; i < 32; i += 8)
        d[(size_t)(n0 + ty + i) * K + k0 + tx] = __float2half(t[tx][ty + i]);
}

// ----------------------------------------------------------------------------
// cp.async 3-stage mma.sync fp16 GEMM, single barrier per K chunk.
// CTA 128x128, K chunk 64, 8 warps (2x4), warp tile 64x32. 96 KB smem, 2 CTA/SM.
// EPI: 2 = bias+residual -> fp32; 3 = bias,q-scale(log2 domain) -> fp16;
//      4 = bias+gelu -> fp16
// ----------------------------------------------------------------------------
#define GS_A 0
#define GS_B 16384
#define GS_STAGE 32768
#define GS_TOTAL (3 * GS_STAGE)   // 96 KB

template <int EPI>
__global__ void __launch_bounds__(256, 2)
tc_gemm(const __half* __restrict__ A, const __half* __restrict__ B,
        const float* __restrict__ bias, const float* __restrict__ res,
        float* __restrict__ Cf, __half* __restrict__ Ch,
        int M, int N, int K) {
    extern __shared__ char smem[];
    uint32_t sb = smem_u32(smem);
    const int tid = threadIdx.x, wid = tid >> 5, lid = tid & 31;
    const int bm = blockIdx.y * 128, bn = blockIdx.x * 128;
    const int wm = (wid & 1) * 64;
    const int wn = (wid >> 1) * 32;

    float acc[4][4][4];
    #pragma unroll
    for (int i = 0; i < 4; i++)
        #pragma unroll
        for (int j = 0; j < 4; j++)
            #pragma unroll
            for (int r = 0; r < 4; r++) acc[i][j][r] = 0.f;

    const int a_r  = lid & 15;
    const int a_kb = (lid >> 4) * 16;
    const int b_row = ((lid >> 4) & 1) * 8 + (lid & 7);
    const int b_kb  = ((lid >> 3) & 1) * 16;

    const int nchunk = K >> 6;
    #define G_LOAD(ck, s) do { \
        const int _k0 = (ck) << 6; \
        uint32_t _dst = sb + (s) * GS_STAGE; \
        _Pragma("unroll") \
        for (int _i = 0; _i < 4; _i++) { \
            int _idx = _i * 256 + tid; \
            int _r = _idx >> 3, _c = (_idx & 7) * 16; \
            uint32_t _so = SWZ128(_r * 128 + _c); \
            cp16(_dst + GS_A + _so, (const char*)(A + (size_t)(bm + _r) * K + _k0) + _c); \
            cp16(_dst + GS_B + _so, (const char*)(B + (size_t)(bn + _r) * K + _k0) + _c); \
        } \
        CP_COMMIT(); \
    } while (0)

    G_LOAD(0, 0);
    G_LOAD(1, 1);
    for (int ck = 0; ck < nchunk; ck++) {
        if (ck + 1 < nchunk) CP_WAIT1();
        else CP_WAIT0();
        __syncthreads();
        if (ck + 2 < nchunk) G_LOAD(ck + 2, (ck + 2) % 3);
        uint32_t stg = sb + (ck % 3) * GS_STAGE;
        #pragma unroll
        for (int ks = 0; ks < 4; ks++) {
            uint32_t a[4][4];
            #pragma unroll
            for (int i = 0; i < 4; i++) {
                uint32_t off = SWZ128((wm + i * 16 + a_r) * 128 + ks * 32 + a_kb);
                ldsm_x4(a[i][0], a[i][1], a[i][2], a[i][3], stg + GS_A + off);
            }
            #pragma unroll
            for (int jp = 0; jp < 2; jp++) {
                uint32_t b0, b1, b2, b3;
                uint32_t off = SWZ128((wn + jp * 16 + b_row) * 128 + ks * 32 + b_kb);
                ldsm_x4(b0, b1, b2, b3, stg + GS_B + off);
                #pragma unroll
                for (int i = 0; i < 4; i++) {
                    mma_f16(acc[i][2 * jp + 0], a[i][0], a[i][1], a[i][2], a[i][3], b0, b1);
                    mma_f16(acc[i][2 * jp + 1], a[i][0], a[i][1], a[i][2], a[i][3], b2, b3);
                }
            }
        }
    }
    #undef G_LOAD

    const int er = lid >> 2;
    const int ec = (lid & 3) * 2;
    #pragma unroll
    for (int i = 0; i < 4; i++) {
        #pragma unroll
        for (int j = 0; j < 4; j++) {
            int col = bn + wn + j * 8 + ec;
            float2 bi = *(const float2*)(bias + col);
            #pragma unroll
            for (int half = 0; half < 2; half++) {
                int row = bm + wm + i * 16 + er + half * 8;
                float ox = acc[i][j][half * 2 + 0] + bi.x;
                float oy = acc[i][j][half * 2 + 1] + bi.y;
                if (EPI == 2) {
                    float2 rv = *(const float2*)(res + (size_t)row * N + col);
                    float2 o = make_float2(ox + rv.x, oy + rv.y);
                    *(float2*)(Cf + (size_t)row * N + col) = o;
                } else {
                    if (EPI == 3) {
                        // q gets 0.125 (both sqrt-scales) * log2(e) so softmax can use exp2
                        float s = ((col % 192) < 64) ? 0.18033688f : 1.0f;
                        ox *= s; oy *= s;
                    }
                    if (EPI == 4) { ox = gelu_fast(ox); oy = gelu_fast(oy); }
                    *(uint32_t*)(Ch + (size_t)row * N + col) = pack_h2(ox, oy);
                }
            }
        }
    }
}

// ----------------------------------------------------------------------------
// LayerNorm -> fp16, one warp per row (8 rows / 256-thread block)
// ----------------------------------------------------------------------------
__global__ void ln_kernel(const float* __restrict__ x, const float* __restrict__ g,
                          const float* __restrict__ beta, __half* __restrict__ yh) {
    int row = blockIdx.x * 8 + (threadIdx.x >> 5);
    int lane = threadIdx.x & 31;
    const float* xr = x + (size_t)row * Ww;
    float4 v[8];
    float s = 0.f, ss = 0.f;
    #pragma unroll
    for (int i = 0; i < 8; i++) {
        v[i] = *(const float4*)(xr + (i * 32 + lane) * 4);
        s  += v[i].x + v[i].y + v[i].z + v[i].w;
        ss += v[i].x * v[i].x + v[i].y * v[i].y + v[i].z * v[i].z + v[i].w * v[i].w;
    }
    #pragma unroll
    for (int off = 16; off; off >>= 1) {
        s  += __shfl_xor_sync(0xffffffffu, s, off);
        ss += __shfl_xor_sync(0xffffffffu, ss, off);
    }
    float mean = s * (1.f / Ww);
    float var  = ss * (1.f / Ww) - mean * mean;
    float rstd = rsqrtf(var + 1e-5f);
    #pragma unroll
    for (int i = 0; i < 8; i++) {
        int c4 = (i * 32 + lane) * 4;
        float4 gv = *(const float4*)(g + c4);
        float4 bv = *(const float4*)(beta + c4);
        float o0 = (v[i].x - mean) * rstd * gv.x + bv.x;
        float o1 = (v[i].y - mean) * rstd * gv.y + bv.y;
        float o2 = (v[i].z - mean) * rstd * gv.z + bv.z;
        float o3 = (v[i].w - mean) * rstd * gv.w + bv.w;
        uint2 o = make_uint2(pack_h2(o0, o1), pack_h2(o2, o3));
        *(uint2*)(yh + (size_t)row * Ww + c4) = o;
    }
}

// ----------------------------------------------------------------------------
// Tensor-core flash attention, fp16; exp2 softmax (log2-domain scores),
// deferred l reduction.
// ----------------------------------------------------------------------------
#define F_Q  0
#define F_ST 16384
#define F_K  0
#define F_V  8192
#define F_STAGE 16384
#define F_TOTAL (F_ST + 3 * F_STAGE)   // 64 KB

__global__ void __launch_bounds__(256, 2)
flash_tc(const __half* __restrict__ qh, __half* __restrict__ oh) {
    extern __shared__ char smem[];
    uint32_t sbm = smem_u32(smem);
    const int tid = threadIdx.x, wid = tid >> 5, lid = tid & 31;
    const int qt = blockIdx.x, h = blockIdx.y, b = blockIdx.z;
    const int wm = wid * 16;

    const size_t hcol = (size_t)h * 192;

    #pragma unroll
    for (int i = 0; i < 4; i++) {
        int idx = i * 256 + tid;
        int r = idx >> 3, c = (idx & 7) * 16;
        uint32_t so = SWZ128(r * 128 + c);
        const char* gq = (const char*)(qh + (size_t)(b * Nn + qt * 128 + r) * (3 * Ww) + hcol) + c;
        cp16(sbm + F_Q + so, gq);
    }
    CP_COMMIT();

    #define F_LOAD(kt, s) do { \
        uint32_t _dst = sbm + F_ST + (s) * F_STAGE; \
        _Pragma("unroll") \
        for (int _i = 0; _i < 2; _i++) { \
            int _idx = _i * 256 + tid; \
            int _r = _idx >> 3, _c = (_idx & 7) * 16; \
            uint32_t _so = SWZ128(_r * 128 + _c); \
            size_t _row = (size_t)(b * Nn + (kt) * 64 + _r) * (3 * Ww) + hcol; \
            cp16(_dst + F_K + _so, (const char*)(qh + _row + 64) + _c); \
            cp16(_dst + F_V + _so, (const char*)(qh + _row + 128) + _c); \
        } \
        CP_COMMIT(); \
    } while (0)

    F_LOAD(0, 0);
    F_LOAD(1, 1);

    const int a_r  = lid & 15;
    const int a_kb = (lid >> 4) * 16;
    const int k_row = ((lid >> 4) & 1) * 8 + (lid & 7);
    const int k_kb  = ((lid >> 3) & 1) * 16;
    const int v_row = ((lid >> 3) & 1) * 8 + (lid & 7);
    const int v_cb  = ((lid >> 4) & 1) * 16;

    float O[8][4];
    #pragma unroll
    for (int j = 0; j < 8; j++)
        #pragma unroll
        for (int r = 0; r < 4; r++) O[j][r] = 0.f;
    float m0 = -INFINITY, m1 = -INFINITY, l0 = 0.f, l1 = 0.f;

    const int NKT = Nn / 64;
    for (int kt = 0; kt < NKT; kt++) {
        if (kt + 1 < NKT) CP_WAIT1();
        else CP_WAIT0();
        __syncthreads();
        if (kt + 2 < NKT) F_LOAD(kt + 2, (kt + 2) % 3);
        uint32_t stg = sbm + F_ST + (kt % 3) * F_STAGE;

        float S[8][4];
        #pragma unroll
        for (int j = 0; j < 8; j++)
            #pragma unroll
            for (int r = 0; r < 4; r++) S[j][r] = 0.f;
        #pragma unroll
        for (int ks = 0; ks < 4; ks++) {
            uint32_t a0, a1, a2, a3;
            ldsm_x4(a0, a1, a2, a3, sbm + F_Q + SWZ128((wm + a_r) * 128 + ks * 32 + a_kb));
            #pragma unroll
            for (int jp = 0; jp < 4; jp++) {
                uint32_t b0, b1, b2, b3;
                uint32_t off = SWZ128((jp * 16 + k_row) * 128 + ks * 32 + k_kb);
                ldsm_x4(b0, b1, b2, b3, stg + F_K + off);
                mma_f16(S[2 * jp + 0], a0, a1, a2, a3, b0, b1);
                mma_f16(S[2 * jp + 1], a0, a1, a2, a3, b2, b3);
            }
        }

        // row max (log2-domain scores)
        float mx0 = -INFINITY, mx1 = -INFINITY;
        #pragma unroll
        for (int j = 0; j < 8; j++) {
            mx0 = fmaxf(mx0, fmaxf(S[j][0], S[j][1]));
            mx1 = fmaxf(mx1, fmaxf(S[j][2], S[j][3]));
        }
        mx0 = fmaxf(mx0, __shfl_xor_sync(0xffffffffu, mx0, 1));
        mx0 = fmaxf(mx0, __shfl_xor_sync(0xffffffffu, mx0, 2));
        mx1 = fmaxf(mx1, __shfl_xor_sync(0xffffffffu, mx1, 1));
        mx1 = fmaxf(mx1, __shfl_xor_sync(0xffffffffu, mx1, 2));
        float nm0 = fmaxf(m0, mx0), nm1 = fmaxf(m1, mx1);
        float al0 = exp2f(m0 - nm0), al1 = exp2f(m1 - nm1);
        m0 = nm0; m1 = nm1;

        // P = 2^(S - m); l kept thread-local (deferred quad reduction)
        uint32_t P[8][2];
        float pl0 = 0.f, pl1 = 0.f;
        #pragma unroll
        for (int j = 0; j < 8; j++) {
            float e0 = exp2f(S[j][0] - nm0);
            float e1 = exp2f(S[j][1] - nm0);
            float e2 = exp2f(S[j][2] - nm1);
            float e3 = exp2f(S[j][3] - nm1);
            pl0 += e0 + e1;
            pl1 += e2 + e3;
            P[j][0] = pack_h2(e0, e1);
            P[j][1] = pack_h2(e2, e3);
        }
        l0 = l0 * al0 + pl0;
        l1 = l1 * al1 + pl1;

        if (!__all_sync(0xffffffffu, (al0 == 1.f) & (al1 == 1.f))) {
            #pragma unroll
            for (int j = 0; j < 8; j++) {
                O[j][0] *= al0; O[j][1] *= al0;
                O[j][2] *= al1; O[j][3] *= al1;
            }
        }

        #pragma unroll
        for (int t = 0; t < 4; t++) {
            uint32_t ph0 = P[2 * t][0], ph1 = P[2 * t][1];
            uint32_t ph2 = P[2 * t + 1][0], ph3 = P[2 * t + 1][1];
            #pragma unroll
            for (int jp = 0; jp < 4; jp++) {
                uint32_t v0, v1, v2, v3;
                uint32_t off = SWZ128((t * 16 + v_row) * 128 + jp * 32 + v_cb);
                ldsm_x4t(v0, v1, v2, v3, stg + F_V + off);
                mma_f16(O[2 * jp + 0], ph0, ph1, ph2, ph3, v0, v1);
                mma_f16(O[2 * jp + 1], ph0, ph1, ph2, ph3, v2, v3);
            }
        }
    }
    #undef F_LOAD

    // final l reduction across the quad
    l0 += __shfl_xor_sync(0xffffffffu, l0, 1);
    l0 += __shfl_xor_sync(0xffffffffu, l0, 2);
    l1 += __shfl_xor_sync(0xffffffffu, l1, 1);
    l1 += __shfl_xor_sync(0xffffffffu, l1, 2);

    float inv0 = 1.f / l0, inv1 = 1.f / l1;
    int r0 = b * Nn + qt * 128 + wm + (lid >> 2);
    int r1 = r0 + 8;
    int cb = h * 64 + (lid & 3) * 2;
    #pragma unroll
    for (int j = 0; j < 8; j++) {
        int col = cb + j * 8;
        *(uint32_t*)(oh + (size_t)r0 * Ww + col) = pack_h2(O[j][0] * inv0, O[j][1] * inv0);
        *(uint32_t*)(oh + (size_t)r1 * Ww + col) = pack_h2(O[j][2] * inv1, O[j][3] * inv1);
    }
}

// ----------------------------------------------------------------------------
// Launcher
// ----------------------------------------------------------------------------
extern "C" void kernel_launch(void* const* d_in, const int* in_sizes, int n_in,
                              void* d_out, int out_size) {
    const float* x      = (const float*)d_in[0];
    const float* ln1_g  = (const float*)d_in[1];
    const float* ln1_b  = (const float*)d_in[2];
    const float* qkv_w  = (const float*)d_in[3];
    const float* qkv_b  = (const float*)d_in[4];
    const float* proj_w = (const float*)d_in[5];
    const float* proj_b = (const float*)d_in[6];
    const float* ln2_g  = (const float*)d_in[7];
    const float* ln2_b  = (const float*)d_in[8];
    const float* fc_w   = (const float*)d_in[9];
    const float* fc_b   = (const float*)d_in[10];
    const float* fc2_w  = (const float*)d_in[11];
    const float* fc2_b  = (const float*)d_in[12];
    float* out = (float*)d_out;

    float* x1;
    __half *ah, *qh, *ath, *hh, *w0, *w1, *w2, *w3;
    cudaGetSymbolAddress((void**)&x1,  g_x1);
    cudaGetSymbolAddress((void**)&ah,  g_ah);
    cudaGetSymbolAddress((void**)&qh,  g_qh);
    cudaGetSymbolAddress((void**)&ath, g_ath);
    cudaGetSymbolAddress((void**)&hh,  g_hh);
    cudaGetSymbolAddress((void**)&w0,  g_w0);
    cudaGetSymbolAddress((void**)&w1,  g_w1);
    cudaGetSymbolAddress((void**)&w2,  g_w2);
    cudaGetSymbolAddress((void**)&w3,  g_w3);

    cudaFuncSetAttribute(tc_gemm<2>, cudaFuncAttributeMaxDynamicSharedMemorySize, GS_TOTAL);
    cudaFuncSetAttribute(tc_gemm<3>, cudaFuncAttributeMaxDynamicSharedMemorySize, GS_TOTAL);
    cudaFuncSetAttribute(tc_gemm<4>, cudaFuncAttributeMaxDynamicSharedMemorySize, GS_TOTAL);
    cudaFuncSetAttribute(flash_tc, cudaFuncAttributeMaxDynamicSharedMemorySize, F_TOTAL);

    convAll_kernel<<<12288, dim3(32, 8)>>>(qkv_w, proj_w, fc_w, fc2_w, w0, w1, w2, w3);

    ln_kernel<<<ROWS / 8, 256>>>(x, ln1_g, ln1_b, ah);
    tc_gemm<3><<<dim3(3 * Ww / 128, ROWS / 128), 256, GS_TOTAL>>>(
        ah, w0, qkv_b, nullptr, nullptr, qh, ROWS, 3 * Ww, Ww);
    flash_tc<<<dim3(Nn / 128, Hh, Bb), 256, F_TOTAL>>>(qh, ath);
    tc_gemm<2><<<dim3(Ww / 128, ROWS / 128), 256, GS_TOTAL>>>(
        ath, w1, proj_b, x, x1, nullptr, ROWS, Ww, Ww);
    ln_kernel<<<ROWS / 8, 256>>>(x1, ln2_g, ln2_b, ah);
    tc_gemm<4><<<dim3(4 * Ww / 128, ROWS / 128), 256, GS_TOTAL>>>(
        ah, w2, fc_b, nullptr, nullptr, hh, ROWS, 4 * Ww, Ww);
    tc_gemm<2><<<dim3(Ww / 128, ROWS / 128), 256, GS_TOTAL>>>(
        hh, w3, fc2_b, x1, out, nullptr, ROWS, Ww, 4 * Ww);
}

// round 15
// speedup vs baseline: 1.0719x; 1.0170x over previous
#include <cuda_runtime.h>
#include <cuda_fp16.h>
#include <math.h>
#include <stdint.h>

// Problem constants
#define Bb 2
#define Nn 2048
#define Ww 1024
#define Hh 16
#define HDd 64
#define ROWS (Bb * Nn)   // 4096

// ----------------------------------------------------------------------------
// Scratch buffers
// ----------------------------------------------------------------------------
__device__ float g_x1[ROWS * Ww];            // post-attention residual (fp32)
__device__ __half g_ah[ROWS * Ww];           // ln output (fp16)
__device__ __half g_qh[ROWS * 3 * Ww];       // qkv (q pre-scaled by 0.125*log2e), fp16
__device__ __half g_ath[ROWS * Ww];          // attention out (fp16)
__device__ __half g_hh[ROWS * 4 * Ww];       // gelu out (fp16)
// converted weights, [N,K] transposed fp16
__device__ __half g_w0[Ww * 3 * Ww];         // qkv_w^T
__device__ __half g_w1[Ww * Ww];             // proj_w^T
__device__ __half g_w2[Ww * 4 * Ww];         // fc_w^T
__device__ __half g_w3[4 * Ww * Ww];         // fc2_w^T

#define SWZ128(off) ((off) ^ (((off) >> 3) & 0x70))

__device__ __forceinline__ uint32_t smem_u32(const void* p) {
    uint32_t a;
    asm("{ .reg .u64 t; cvta.to.shared.u64 t, %1; cvt.u32.u64 %0, t; }" : "=r"(a) : "l"(p));
    return a;
}
__device__ __forceinline__ void cp16(uint32_t saddr, const void* g) {
    asm volatile("cp.async.cg.shared.global [%0], [%1], 16;" :: "r"(saddr), "l"(g));
}
#define CP_COMMIT() asm volatile("cp.async.commit_group;" ::: "memory")
#define CP_WAIT1()  asm volatile("cp.async.wait_group 1;" ::: "memory")
#define CP_WAIT0()  asm volatile("cp.async.wait_group 0;" ::: "memory")

__device__ __forceinline__ void ldsm_x4(uint32_t& a0, uint32_t& a1, uint32_t& a2, uint32_t& a3,
                                        uint32_t addr) {
    asm volatile("ldmatrix.sync.aligned.m8n8.x4.shared.b16 {%0,%1,%2,%3}, [%4];"
                 : "=r"(a0), "=r"(a1), "=r"(a2), "=r"(a3) : "r"(addr));
}
__device__ __forceinline__ void ldsm_x4t(uint32_t& a0, uint32_t& a1, uint32_t& a2, uint32_t& a3,
                                         uint32_t addr) {
    asm volatile("ldmatrix.sync.aligned.m8n8.x4.trans.shared.b16 {%0,%1,%2,%3}, [%4];"
                 : "=r"(a0), "=r"(a1), "=r"(a2), "=r"(a3) : "r"(addr));
}
__device__ __forceinline__ void mma_f16(float* c,
                                        uint32_t a0, uint32_t a1, uint32_t a2, uint32_t a3,
                                        uint32_t b0, uint32_t b1) {
    asm volatile(
        "mma.sync.aligned.m16n8k16.row.col.f32.f16.f16.f32 "
        "{%0,%1,%2,%3}, {%4,%5,%6,%7}, {%8,%9}, {%0,%1,%2,%3};"
        : "+f"(c[0]), "+f"(c[1]), "+f"(c[2]), "+f"(c[3])
        : "r"(a0), "r"(a1), "r"(a2), "r"(a3), "r"(b0), "r"(b1));
}
__device__ __forceinline__ uint32_t pack_h2(float a, float b) {
    __half2 t = __floats2half2_rn(a, b);
    return *(uint32_t*)&t;
}
// tanh-form GELU via single EX2 + fast reciprocal
__device__ __forceinline__ float gelu_fast(float x) {
    float x2 = x * x;
    float u = fmaf(0.044715f * x2, x, x);
    float z = exp2f(2.3021183f * u);
    return x * __fdividef(z, z + 1.0f);
}

// ----------------------------------------------------------------------------
// convAll: convert+transpose all 4 weights in ONE launch.
// ----------------------------------------------------------------------------
__global__ void convAll_kernel(const float* __restrict__ w0, const float* __restrict__ w1,
                               const float* __restrict__ w2, const float* __restrict__ w3,
                               __half* __restrict__ d0, __half* __restrict__ d1,
                               __half* __restrict__ d2, __half* __restrict__ d3) {
    __shared__ float t[32][33];
    int id = blockIdx.x;
    const float* w; __half* d; int K, N;
    if (id < 3072)      { w = w0; d = d0; K = Ww;     N = 3 * Ww; }
    else if (id < 4096) { w = w1; d = d1; K = Ww;     N = Ww;     id -= 3072; }
    else if (id < 8192) { w = w2; d = d2; K = Ww;     N = 4 * Ww; id -= 4096; }
    else                { w = w3; d = d3; K = 4 * Ww; N = Ww;     id -= 8192; }
    int nx = N >> 5;
    int n0 = (id % nx) * 32, k0 = (id / nx) * 32;
    int tx = threadIdx.x, ty = threadIdx.y;   // 32 x 8
    #pragma unroll
    for (int i = 0; i < 32; i += 8)
        t[ty + i][tx] = w[(size_t)(k0 + ty + i) * N + n0 + tx];
    __syncthreads();
    #pragma unroll
    for (int i = 0; i < 32; i += 8)
        d[(size_t)(n0 + ty + i) * K + k0 + tx] = __float2half(t[tx][ty + i]);
}

// ----------------------------------------------------------------------------
// cp.async 3-stage mma.sync fp16 GEMM, single barrier per K chunk,
// ks-level fragment double-buffering (ldsm of ks+1 overlaps MMAs of ks).
// CTA 128x128, K chunk 64, 8 warps (2x4), warp tile 64x32. 96 KB smem, 2 CTA/SM.
// EPI: 2 = bias+residual -> fp32; 3 = bias,q-scale(log2 domain) -> fp16;
//      4 = bias+gelu -> fp16
// ----------------------------------------------------------------------------
#define GS_A 0
#define GS_B 16384
#define GS_STAGE 32768
#define GS_TOTAL (3 * GS_STAGE)   // 96 KB

template <int EPI>
__global__ void __launch_bounds__(256, 2)
tc_gemm(const __half* __restrict__ A, const __half* __restrict__ B,
        const float* __restrict__ bias, const float* __restrict__ res,
        float* __restrict__ Cf, __half* __restrict__ Ch,
        int M, int N, int K) {
    extern __shared__ char smem[];
    uint32_t sb = smem_u32(smem);
    const int tid = threadIdx.x, wid = tid >> 5, lid = tid & 31;
    const int bm = blockIdx.y * 128, bn = blockIdx.x * 128;
    const int wm = (wid & 1) * 64;
    const int wn = (wid >> 1) * 32;

    float acc[4][4][4];
    #pragma unroll
    for (int i = 0; i < 4; i++)
        #pragma unroll
        for (int j = 0; j < 4; j++)
            #pragma unroll
            for (int r = 0; r < 4; r++) acc[i][j][r] = 0.f;

    const int a_r  = lid & 15;
    const int a_kb = (lid >> 4) * 16;
    const int b_row = ((lid >> 4) & 1) * 8 + (lid & 7);
    const int b_kb  = ((lid >> 3) & 1) * 16;

    const int nchunk = K >> 6;
    #define G_LOAD(ck, s) do { \
        const int _k0 = (ck) << 6; \
        uint32_t _dst = sb + (s) * GS_STAGE; \
        _Pragma("unroll") \
        for (int _i = 0; _i < 4; _i++) { \
            int _idx = _i * 256 + tid; \
            int _r = _idx >> 3, _c = (_idx & 7) * 16; \
            uint32_t _so = SWZ128(_r * 128 + _c); \
            cp16(_dst + GS_A + _so, (const char*)(A + (size_t)(bm + _r) * K + _k0) + _c); \
            cp16(_dst + GS_B + _so, (const char*)(B + (size_t)(bn + _r) * K + _k0) + _c); \
        } \
        CP_COMMIT(); \
    } while (0)

    // fragment buffers (double-buffered at ks granularity)
    uint32_t af[2][4][4], bf[2][2][4];
    #define LD_FRAG(ks, buf) do { \
        _Pragma("unroll") \
        for (int _i = 0; _i < 4; _i++) \
            ldsm_x4(af[buf][_i][0], af[buf][_i][1], af[buf][_i][2], af[buf][_i][3], \
                    stg + GS_A + SWZ128((wm + _i * 16 + a_r) * 128 + (ks) * 32 + a_kb)); \
        _Pragma("unroll") \
        for (int _jp = 0; _jp < 2; _jp++) \
            ldsm_x4(bf[buf][_jp][0], bf[buf][_jp][1], bf[buf][_jp][2], bf[buf][_jp][3], \
                    stg + GS_B + SWZ128((wn + _jp * 16 + b_row) * 128 + (ks) * 32 + b_kb)); \
    } while (0)

    G_LOAD(0, 0);
    G_LOAD(1, 1);
    for (int ck = 0; ck < nchunk; ck++) {
        if (ck + 1 < nchunk) CP_WAIT1();
        else CP_WAIT0();
        __syncthreads();
        if (ck + 2 < nchunk) G_LOAD(ck + 2, (ck + 2) % 3);
        uint32_t stg = sb + (ck % 3) * GS_STAGE;
        LD_FRAG(0, 0);
        #pragma unroll
        for (int ks = 0; ks < 4; ks++) {
            const int cur = ks & 1;
            if (ks < 3) LD_FRAG(ks + 1, cur ^ 1);
            #pragma unroll
            for (int jp = 0; jp < 2; jp++) {
                #pragma unroll
                for (int i = 0; i < 4; i++) {
                    mma_f16(acc[i][2 * jp + 0], af[cur][i][0], af[cur][i][1],
                            af[cur][i][2], af[cur][i][3], bf[cur][jp][0], bf[cur][jp][1]);
                    mma_f16(acc[i][2 * jp + 1], af[cur][i][0], af[cur][i][1],
                            af[cur][i][2], af[cur][i][3], bf[cur][jp][2], bf[cur][jp][3]);
                }
            }
        }
    }
    #undef LD_FRAG
    #undef G_LOAD

    const int er = lid >> 2;
    const int ec = (lid & 3) * 2;
    #pragma unroll
    for (int i = 0; i < 4; i++) {
        #pragma unroll
        for (int j = 0; j < 4; j++) {
            int col = bn + wn + j * 8 + ec;
            float2 bi = *(const float2*)(bias + col);
            #pragma unroll
            for (int half = 0; half < 2; half++) {
                int row = bm + wm + i * 16 + er + half * 8;
                float ox = acc[i][j][half * 2 + 0] + bi.x;
                float oy = acc[i][j][half * 2 + 1] + bi.y;
                if (EPI == 2) {
                    float2 rv = *(const float2*)(res + (size_t)row * N + col);
                    float2 o = make_float2(ox + rv.x, oy + rv.y);
                    *(float2*)(Cf + (size_t)row * N + col) = o;
                } else {
                    if (EPI == 3) {
                        // q gets 0.125 (both sqrt-scales) * log2(e) so softmax can use exp2
                        float s = ((col % 192) < 64) ? 0.18033688f : 1.0f;
                        ox *= s; oy *= s;
                    }
                    if (EPI == 4) { ox = gelu_fast(ox); oy = gelu_fast(oy); }
                    *(uint32_t*)(Ch + (size_t)row * N + col) = pack_h2(ox, oy);
                }
            }
        }
    }
}

// ----------------------------------------------------------------------------
// LayerNorm -> fp16, one warp per row (8 rows / 256-thread block)
// ----------------------------------------------------------------------------
__global__ void ln_kernel(const float* __restrict__ x, const float* __restrict__ g,
                          const float* __restrict__ beta, __half* __restrict__ yh) {
    int row = blockIdx.x * 8 + (threadIdx.x >> 5);
    int lane = threadIdx.x & 31;
    const float* xr = x + (size_t)row * Ww;
    float4 v[8];
    float s = 0.f, ss = 0.f;
    #pragma unroll
    for (int i = 0; i < 8; i++) {
        v[i] = *(const float4*)(xr + (i * 32 + lane) * 4);
        s  += v[i].x + v[i].y + v[i].z + v[i].w;
        ss += v[i].x * v[i].x + v[i].y * v[i].y + v[i].z * v[i].z + v[i].w * v[i].w;
    }
    #pragma unroll
    for (int off = 16; off; off >>= 1) {
        s  += __shfl_xor_sync(0xffffffffu, s, off);
        ss += __shfl_xor_sync(0xffffffffu, ss, off);
    }
    float mean = s * (1.f / Ww);
    float var  = ss * (1.f / Ww) - mean * mean;
    float rstd = rsqrtf(var + 1e-5f);
    #pragma unroll
    for (int i = 0; i < 8; i++) {
        int c4 = (i * 32 + lane) * 4;
        float4 gv = *(const float4*)(g + c4);
        float4 bv = *(const float4*)(beta + c4);
        float o0 = (v[i].x - mean) * rstd * gv.x + bv.x;
        float o1 = (v[i].y - mean) * rstd * gv.y + bv.y;
        float o2 = (v[i].z - mean) * rstd * gv.z + bv.z;
        float o3 = (v[i].w - mean) * rstd * gv.w + bv.w;
        uint2 o = make_uint2(pack_h2(o0, o1), pack_h2(o2, o3));
        *(uint2*)(yh + (size_t)row * Ww + c4) = o;
    }
}

// ----------------------------------------------------------------------------
// Tensor-core flash attention, fp16; exp2 softmax (log2-domain scores),
// deferred l reduction.  (unchanged from R13/R14 winner)
// ----------------------------------------------------------------------------
#define F_Q  0
#define F_ST 16384
#define F_K  0
#define F_V  8192
#define F_STAGE 16384
#define F_TOTAL (F_ST + 3 * F_STAGE)   // 64 KB

__global__ void __launch_bounds__(256, 2)
flash_tc(const __half* __restrict__ qh, __half* __restrict__ oh) {
    extern __shared__ char smem[];
    uint32_t sbm = smem_u32(smem);
    const int tid = threadIdx.x, wid = tid >> 5, lid = tid & 31;
    const int qt = blockIdx.x, h = blockIdx.y, b = blockIdx.z;
    const int wm = wid * 16;

    const size_t hcol = (size_t)h * 192;

    #pragma unroll
    for (int i = 0; i < 4; i++) {
        int idx = i * 256 + tid;
        int r = idx >> 3, c = (idx & 7) * 16;
        uint32_t so = SWZ128(r * 128 + c);
        const char* gq = (const char*)(qh + (size_t)(b * Nn + qt * 128 + r) * (3 * Ww) + hcol) + c;
        cp16(sbm + F_Q + so, gq);
    }
    CP_COMMIT();

    #define F_LOAD(kt, s) do { \
        uint32_t _dst = sbm + F_ST + (s) * F_STAGE; \
        _Pragma("unroll") \
        for (int _i = 0; _i < 2; _i++) { \
            int _idx = _i * 256 + tid; \
            int _r = _idx >> 3, _c = (_idx & 7) * 16; \
            uint32_t _so = SWZ128(_r * 128 + _c); \
            size_t _row = (size_t)(b * Nn + (kt) * 64 + _r) * (3 * Ww) + hcol; \
            cp16(_dst + F_K + _so, (const char*)(qh + _row + 64) + _c); \
            cp16(_dst + F_V + _so, (const char*)(qh + _row + 128) + _c); \
        } \
        CP_COMMIT(); \
    } while (0)

    F_LOAD(0, 0);
    F_LOAD(1, 1);

    const int a_r  = lid & 15;
    const int a_kb = (lid >> 4) * 16;
    const int k_row = ((lid >> 4) & 1) * 8 + (lid & 7);
    const int k_kb  = ((lid >> 3) & 1) * 16;
    const int v_row = ((lid >> 3) & 1) * 8 + (lid & 7);
    const int v_cb  = ((lid >> 4) & 1) * 16;

    float O[8][4];
    #pragma unroll
    for (int j = 0; j < 8; j++)
        #pragma unroll
        for (int r = 0; r < 4; r++) O[j][r] = 0.f;
    float m0 = -INFINITY, m1 = -INFINITY, l0 = 0.f, l1 = 0.f;

    const int NKT = Nn / 64;
    for (int kt = 0; kt < NKT; kt++) {
        if (kt + 1 < NKT) CP_WAIT1();
        else CP_WAIT0();
        __syncthreads();
        if (kt + 2 < NKT) F_LOAD(kt + 2, (kt + 2) % 3);
        uint32_t stg = sbm + F_ST + (kt % 3) * F_STAGE;

        float S[8][4];
        #pragma unroll
        for (int j = 0; j < 8; j++)
            #pragma unroll
            for (int r = 0; r < 4; r++) S[j][r] = 0.f;
        #pragma unroll
        for (int ks = 0; ks < 4; ks++) {
            uint32_t a0, a1, a2, a3;
            ldsm_x4(a0, a1, a2, a3, sbm + F_Q + SWZ128((wm + a_r) * 128 + ks * 32 + a_kb));
            #pragma unroll
            for (int jp = 0; jp < 4; jp++) {
                uint32_t b0, b1, b2, b3;
                uint32_t off = SWZ128((jp * 16 + k_row) * 128 + ks * 32 + k_kb);
                ldsm_x4(b0, b1, b2, b3, stg + F_K + off);
                mma_f16(S[2 * jp + 0], a0, a1, a2, a3, b0, b1);
                mma_f16(S[2 * jp + 1], a0, a1, a2, a3, b2, b3);
            }
        }

        float mx0 = -INFINITY, mx1 = -INFINITY;
        #pragma unroll
        for (int j = 0; j < 8; j++) {
            mx0 = fmaxf(mx0, fmaxf(S[j][0], S[j][1]));
            mx1 = fmaxf(mx1, fmaxf(S[j][2], S[j][3]));
        }
        mx0 = fmaxf(mx0, __shfl_xor_sync(0xffffffffu, mx0, 1));
        mx0 = fmaxf(mx0, __shfl_xor_sync(0xffffffffu, mx0, 2));
        mx1 = fmaxf(mx1, __shfl_xor_sync(0xffffffffu, mx1, 1));
        mx1 = fmaxf(mx1, __shfl_xor_sync(0xffffffffu, mx1, 2));
        float nm0 = fmaxf(m0, mx0), nm1 = fmaxf(m1, mx1);
        float al0 = exp2f(m0 - nm0), al1 = exp2f(m1 - nm1);
        m0 = nm0; m1 = nm1;

        uint32_t P[8][2];
        float pl0 = 0.f, pl1 = 0.f;
        #pragma unroll
        for (int j = 0; j < 8; j++) {
            float e0 = exp2f(S[j][0] - nm0);
            float e1 = exp2f(S[j][1] - nm0);
            float e2 = exp2f(S[j][2] - nm1);
            float e3 = exp2f(S[j][3] - nm1);
            pl0 += e0 + e1;
            pl1 += e2 + e3;
            P[j][0] = pack_h2(e0, e1);
            P[j][1] = pack_h2(e2, e3);
        }
        l0 = l0 * al0 + pl0;
        l1 = l1 * al1 + pl1;

        if (!__all_sync(0xffffffffu, (al0 == 1.f) & (al1 == 1.f))) {
            #pragma unroll
            for (int j = 0; j < 8; j++) {
                O[j][0] *= al0; O[j][1] *= al0;
                O[j][2] *= al1; O[j][3] *= al1;
            }
        }

        #pragma unroll
        for (int t = 0; t < 4; t++) {
            uint32_t ph0 = P[2 * t][0], ph1 = P[2 * t][1];
            uint32_t ph2 = P[2 * t + 1][0], ph3 = P[2 * t + 1][1];
            #pragma unroll
            for (int jp = 0; jp < 4; jp++) {
                uint32_t v0, v1, v2, v3;
                uint32_t off = SWZ128((t * 16 + v_row) * 128 + jp * 32 + v_cb);
                ldsm_x4t(v0, v1, v2, v3, stg + F_V + off);
                mma_f16(O[2 * jp + 0], ph0, ph1, ph2, ph3, v0, v1);
                mma_f16(O[2 * jp + 1], ph0, ph1, ph2, ph3, v2, v3);
            }
        }
    }
    #undef F_LOAD

    l0 += __shfl_xor_sync(0xffffffffu, l0, 1);
    l0 += __shfl_xor_sync(0xffffffffu, l0, 2);
    l1 += __shfl_xor_sync(0xffffffffu, l1, 1);
    l1 += __shfl_xor_sync(0xffffffffu, l1, 2);

    float inv0 = 1.f / l0, inv1 = 1.f / l1;
    int r0 = b * Nn + qt * 128 + wm + (lid >> 2);
    int r1 = r0 + 8;
    int cb = h * 64 + (lid & 3) * 2;
    #pragma unroll
    for (int j = 0; j < 8; j++) {
        int col = cb + j * 8;
        *(uint32_t*)(oh + (size_t)r0 * Ww + col) = pack_h2(O[j][0] * inv0, O[j][1] * inv0);
        *(uint32_t*)(oh + (size_t)r1 * Ww + col) = pack_h2(O[j][2] * inv1, O[j][3] * inv1);
    }
}

// ----------------------------------------------------------------------------
// Launcher
// ----------------------------------------------------------------------------
extern "C" void kernel_launch(void* const* d_in, const int* in_sizes, int n_in,
                              void* d_out, int out_size) {
    const float* x      = (const float*)d_in[0];
    const float* ln1_g  = (const float*)d_in[1];
    const float* ln1_b  = (const float*)d_in[2];
    const float* qkv_w  = (const float*)d_in[3];
    const float* qkv_b  = (const float*)d_in[4];
    const float* proj_w = (const float*)d_in[5];
    const float* proj_b = (const float*)d_in[6];
    const float* ln2_g  = (const float*)d_in[7];
    const float* ln2_b  = (const float*)d_in[8];
    const float* fc_w   = (const float*)d_in[9];
    const float* fc_b   = (const float*)d_in[10];
    const float* fc2_w  = (const float*)d_in[11];
    const float* fc2_b  = (const float*)d_in[12];
    float* out = (float*)d_out;

    float* x1;
    __half *ah, *qh, *ath, *hh, *w0, *w1, *w2, *w3;
    cudaGetSymbolAddress((void**)&x1,  g_x1);
    cudaGetSymbolAddress((void**)&ah,  g_ah);
    cudaGetSymbolAddress((void**)&qh,  g_qh);
    cudaGetSymbolAddress((void**)&ath, g_ath);
    cudaGetSymbolAddress((void**)&hh,  g_hh);
    cudaGetSymbolAddress((void**)&w0,  g_w0);
    cudaGetSymbolAddress((void**)&w1,  g_w1);
    cudaGetSymbolAddress((void**)&w2,  g_w2);
    cudaGetSymbolAddress((void**)&w3,  g_w3);

    cudaFuncSetAttribute(tc_gemm<2>, cudaFuncAttributeMaxDynamicSharedMemorySize, GS_TOTAL);
    cudaFuncSetAttribute(tc_gemm<3>, cudaFuncAttributeMaxDynamicSharedMemorySize, GS_TOTAL);
    cudaFuncSetAttribute(tc_gemm<4>, cudaFuncAttributeMaxDynamicSharedMemorySize, GS_TOTAL);
    cudaFuncSetAttribute(flash_tc, cudaFuncAttributeMaxDynamicSharedMemorySize, F_TOTAL);

    convAll_kernel<<<12288, dim3(32, 8)>>>(qkv_w, proj_w, fc_w, fc2_w, w0, w1, w2, w3);

    ln_kernel<<<ROWS / 8, 256>>>(x, ln1_g, ln1_b, ah);
    tc_gemm<3><<<dim3(3 * Ww / 128, ROWS / 128), 256, GS_TOTAL>>>(
        ah, w0, qkv_b, nullptr, nullptr, qh, ROWS, 3 * Ww, Ww);
    flash_tc<<<dim3(Nn / 128, Hh, Bb), 256, F_TOTAL>>>(qh, ath);
    tc_gemm<2><<<dim3(Ww / 128, ROWS / 128), 256, GS_TOTAL>>>(
        ath, w1, proj_b, x, x1, nullptr, ROWS, Ww, Ww);
    ln_kernel<<<ROWS / 8, 256>>>(x1, ln2_g, ln2_b, ah);
    tc_gemm<4><<<dim3(4 * Ww / 128, ROWS / 128), 256, GS_TOTAL>>>(
        ah, w2, fc_b, nullptr, nullptr, hh, ROWS, 4 * Ww, Ww);
    tc_gemm<2><<<dim3(Ww / 128, ROWS / 128), 256, GS_TOTAL>>>(
        hh, w3, fc2_b, x1, out, nullptr, ROWS, Ww, 4 * Ww);
}

// round 16
// speedup vs baseline: 1.0727x; 1.0007x over previous
#include <cuda_runtime.h>
#include <cuda_fp16.h>
#include <math.h>
#include <stdint.h>

// Problem constants
#define Bb 2
#define Nn 2048
#define Ww 1024
#define Hh 16
#define HDd 64
#define ROWS (Bb * Nn)   // 4096

// ----------------------------------------------------------------------------
// Scratch buffers
// ----------------------------------------------------------------------------
__device__ float g_x1[ROWS * Ww];            // post-attention residual (fp32)
__device__ __half g_ah[ROWS * Ww];           // ln output (fp16)
__device__ __half g_qh[ROWS * 3 * Ww];       // qkv (q pre-scaled by 0.125*log2e), fp16
__device__ __half g_ath[ROWS * Ww];          // attention out (fp16)
__device__ __half g_hh[ROWS * 4 * Ww];       // gelu out (fp16)
// converted weights, [N,K] transposed fp16
__device__ __half g_w0[Ww * 3 * Ww];         // qkv_w^T
__device__ __half g_w1[Ww * Ww];             // proj_w^T
__device__ __half g_w2[Ww * 4 * Ww];         // fc_w^T
__device__ __half g_w3[4 * Ww * Ww];         // fc2_w^T

#define SWZ128(off) ((off) ^ (((off) >> 3) & 0x70))

__device__ __forceinline__ uint32_t smem_u32(const void* p) {
    uint32_t a;
    asm("{ .reg .u64 t; cvta.to.shared.u64 t, %1; cvt.u32.u64 %0, t; }" : "=r"(a) : "l"(p));
    return a;
}
__device__ __forceinline__ void cp16(uint32_t saddr, const void* g) {
    asm volatile("cp.async.cg.shared.global [%0], [%1], 16;" :: "r"(saddr), "l"(g));
}
#define CP_COMMIT() asm volatile("cp.async.commit_group;" ::: "memory")
#define CP_WAIT1()  asm volatile("cp.async.wait_group 1;" ::: "memory")
#define CP_WAIT0()  asm volatile("cp.async.wait_group 0;" ::: "memory")

__device__ __forceinline__ void ldsm_x4(uint32_t& a0, uint32_t& a1, uint32_t& a2, uint32_t& a3,
                                        uint32_t addr) {
    asm volatile("ldmatrix.sync.aligned.m8n8.x4.shared.b16 {%0,%1,%2,%3}, [%4];"
                 : "=r"(a0), "=r"(a1), "=r"(a2), "=r"(a3) : "r"(addr));
}
__device__ __forceinline__ void ldsm_x4t(uint32_t& a0, uint32_t& a1, uint32_t& a2, uint32_t& a3,
                                         uint32_t addr) {
    asm volatile("ldmatrix.sync.aligned.m8n8.x4.trans.shared.b16 {%0,%1,%2,%3}, [%4];"
                 : "=r"(a0), "=r"(a1), "=r"(a2), "=r"(a3) : "r"(addr));
}
__device__ __forceinline__ void mma_f16(float* c,
                                        uint32_t a0, uint32_t a1, uint32_t a2, uint32_t a3,
                                        uint32_t b0, uint32_t b1) {
    asm volatile(
        "mma.sync.aligned.m16n8k16.row.col.f32.f16.f16.f32 "
        "{%0,%1,%2,%3}, {%4,%5,%6,%7}, {%8,%9}, {%0,%1,%2,%3};"
        : "+f"(c[0]), "+f"(c[1]), "+f"(c[2]), "+f"(c[3])
        : "r"(a0), "r"(a1), "r"(a2), "r"(a3), "r"(b0), "r"(b1));
}
__device__ __forceinline__ uint32_t pack_h2(float a, float b) {
    __half2 t = __floats2half2_rn(a, b);
    return *(uint32_t*)&t;
}
// tanh-form GELU via single EX2 + fast reciprocal
__device__ __forceinline__ float gelu_fast(float x) {
    float x2 = x * x;
    float u = fmaf(0.044715f * x2, x, x);
    float z = exp2f(2.3021183f * u);
    return x * __fdividef(z, z + 1.0f);
}

// ----------------------------------------------------------------------------
// convAll: convert+transpose all 4 weights in ONE launch; vectorized stores.
// ----------------------------------------------------------------------------
__global__ void convAll_kernel(const float* __restrict__ w0, const float* __restrict__ w1,
                               const float* __restrict__ w2, const float* __restrict__ w3,
                               __half* __restrict__ d0, __half* __restrict__ d1,
                               __half* __restrict__ d2, __half* __restrict__ d3) {
    __shared__ float t[32][33];
    int id = blockIdx.x;
    const float* w; __half* d; int K, N;
    if (id < 3072)      { w = w0; d = d0; K = Ww;     N = 3 * Ww; }
    else if (id < 4096) { w = w1; d = d1; K = Ww;     N = Ww;     id -= 3072; }
    else if (id < 8192) { w = w2; d = d2; K = Ww;     N = 4 * Ww; id -= 4096; }
    else                { w = w3; d = d3; K = 4 * Ww; N = Ww;     id -= 8192; }
    int nx = N >> 5;
    int n0 = (id % nx) * 32, k0 = (id / nx) * 32;
    int tid = threadIdx.y * 32 + threadIdx.x;  // 256 threads
    int tx = threadIdx.x, ty = threadIdx.y;    // 32 x 8
    #pragma unroll
    for (int i = 0; i < 32; i += 8)
        t[ty + i][tx] = w[(size_t)(k0 + ty + i) * N + n0 + tx];
    __syncthreads();
    // output: row = n-index (32), cgrp = 4-wide k group (8); one uint2 per thread
    int row = tid >> 3;
    int c4  = (tid & 7) * 4;
    __half h0 = __float2half(t[c4 + 0][row]);
    __half h1 = __float2half(t[c4 + 1][row]);
    __half h2 = __float2half(t[c4 + 2][row]);
    __half h3 = __float2half(t[c4 + 3][row]);
    uint2 o;
    __half2 p0 = __halves2half2(h0, h1), p1 = __halves2half2(h2, h3);
    o.x = *(uint32_t*)&p0;
    o.y = *(uint32_t*)&p1;
    *(uint2*)(d + (size_t)(n0 + row) * K + k0 + c4) = o;
}

// ----------------------------------------------------------------------------
// cp.async 3-stage mma.sync fp16 GEMM, single barrier per K chunk,
// ks-level fragment double-buffering.
// CTA 128x128, K chunk 64, 8 warps (2x4), warp tile 64x32. 96 KB smem, 2 CTA/SM.
// EPI: 2 = bias+residual -> fp32; 3 = bias,q-scale(log2 domain) -> fp16;
//      4 = bias+gelu -> fp16
// ----------------------------------------------------------------------------
#define GS_A 0
#define GS_B 16384
#define GS_STAGE 32768
#define GS_TOTAL (3 * GS_STAGE)   // 96 KB

template <int EPI>
__global__ void __launch_bounds__(256, 2)
tc_gemm(const __half* __restrict__ A, const __half* __restrict__ B,
        const float* __restrict__ bias, const float* __restrict__ res,
        float* __restrict__ Cf, __half* __restrict__ Ch,
        int M, int N, int K) {
    extern __shared__ char smem[];
    uint32_t sb = smem_u32(smem);
    const int tid = threadIdx.x, wid = tid >> 5, lid = tid & 31;
    const int bm = blockIdx.y * 128, bn = blockIdx.x * 128;
    const int wm = (wid & 1) * 64;
    const int wn = (wid >> 1) * 32;

    float acc[4][4][4];
    #pragma unroll
    for (int i = 0; i < 4; i++)
        #pragma unroll
        for (int j = 0; j < 4; j++)
            #pragma unroll
            for (int r = 0; r < 4; r++) acc[i][j][r] = 0.f;

    const int a_r  = lid & 15;
    const int a_kb = (lid >> 4) * 16;
    const int b_row = ((lid >> 4) & 1) * 8 + (lid & 7);
    const int b_kb  = ((lid >> 3) & 1) * 16;

    const int nchunk = K >> 6;
    #define G_LOAD(ck, s) do { \
        const int _k0 = (ck) << 6; \
        uint32_t _dst = sb + (s) * GS_STAGE; \
        _Pragma("unroll") \
        for (int _i = 0; _i < 4; _i++) { \
            int _idx = _i * 256 + tid; \
            int _r = _idx >> 3, _c = (_idx & 7) * 16; \
            uint32_t _so = SWZ128(_r * 128 + _c); \
            cp16(_dst + GS_A + _so, (const char*)(A + (size_t)(bm + _r) * K + _k0) + _c); \
            cp16(_dst + GS_B + _so, (const char*)(B + (size_t)(bn + _r) * K + _k0) + _c); \
        } \
        CP_COMMIT(); \
    } while (0)

    uint32_t af[2][4][4], bf[2][2][4];
    #define LD_FRAG(ks, buf) do { \
        _Pragma("unroll") \
        for (int _i = 0; _i < 4; _i++) \
            ldsm_x4(af[buf][_i][0], af[buf][_i][1], af[buf][_i][2], af[buf][_i][3], \
                    stg + GS_A + SWZ128((wm + _i * 16 + a_r) * 128 + (ks) * 32 + a_kb)); \
        _Pragma("unroll") \
        for (int _jp = 0; _jp < 2; _jp++) \
            ldsm_x4(bf[buf][_jp][0], bf[buf][_jp][1], bf[buf][_jp][2], bf[buf][_jp][3], \
                    stg + GS_B + SWZ128((wn + _jp * 16 + b_row) * 128 + (ks) * 32 + b_kb)); \
    } while (0)

    G_LOAD(0, 0);
    G_LOAD(1, 1);
    for (int ck = 0; ck < nchunk; ck++) {
        if (ck + 1 < nchunk) CP_WAIT1();
        else CP_WAIT0();
        __syncthreads();
        if (ck + 2 < nchunk) G_LOAD(ck + 2, (ck + 2) % 3);
        uint32_t stg = sb + (ck % 3) * GS_STAGE;
        LD_FRAG(0, 0);
        #pragma unroll
        for (int ks = 0; ks < 4; ks++) {
            const int cur = ks & 1;
            if (ks < 3) LD_FRAG(ks + 1, cur ^ 1);
            #pragma unroll
            for (int jp = 0; jp < 2; jp++) {
                #pragma unroll
                for (int i = 0; i < 4; i++) {
                    mma_f16(acc[i][2 * jp + 0], af[cur][i][0], af[cur][i][1],
                            af[cur][i][2], af[cur][i][3], bf[cur][jp][0], bf[cur][jp][1]);
                    mma_f16(acc[i][2 * jp + 1], af[cur][i][0], af[cur][i][1],
                            af[cur][i][2], af[cur][i][3], bf[cur][jp][2], bf[cur][jp][3]);
                }
            }
        }
    }
    #undef LD_FRAG
    #undef G_LOAD

    const int er = lid >> 2;
    const int ec = (lid & 3) * 2;
    #pragma unroll
    for (int i = 0; i < 4; i++) {
        #pragma unroll
        for (int j = 0; j < 4; j++) {
            int col = bn + wn + j * 8 + ec;
            float2 bi = *(const float2*)(bias + col);
            #pragma unroll
            for (int half = 0; half < 2; half++) {
                int row = bm + wm + i * 16 + er + half * 8;
                float ox = acc[i][j][half * 2 + 0] + bi.x;
                float oy = acc[i][j][half * 2 + 1] + bi.y;
                if (EPI == 2) {
                    float2 rv = *(const float2*)(res + (size_t)row * N + col);
                    float2 o = make_float2(ox + rv.x, oy + rv.y);
                    *(float2*)(Cf + (size_t)row * N + col) = o;
                } else {
                    if (EPI == 3) {
                        float s = ((col % 192) < 64) ? 0.18033688f : 1.0f;
                        ox *= s; oy *= s;
                    }
                    if (EPI == 4) { ox = gelu_fast(ox); oy = gelu_fast(oy); }
                    *(uint32_t*)(Ch + (size_t)row * N + col) = pack_h2(ox, oy);
                }
            }
        }
    }
}

// ----------------------------------------------------------------------------
// LayerNorm -> fp16, one warp per row (8 rows / 256-thread block)
// ----------------------------------------------------------------------------
__global__ void ln_kernel(const float* __restrict__ x, const float* __restrict__ g,
                          const float* __restrict__ beta, __half* __restrict__ yh) {
    int row = blockIdx.x * 8 + (threadIdx.x >> 5);
    int lane = threadIdx.x & 31;
    const float* xr = x + (size_t)row * Ww;
    float4 v[8];
    float s = 0.f, ss = 0.f;
    #pragma unroll
    for (int i = 0; i < 8; i++) {
        v[i] = *(const float4*)(xr + (i * 32 + lane) * 4);
        s  += v[i].x + v[i].y + v[i].z + v[i].w;
        ss += v[i].x * v[i].x + v[i].y * v[i].y + v[i].z * v[i].z + v[i].w * v[i].w;
    }
    #pragma unroll
    for (int off = 16; off; off >>= 1) {
        s  += __shfl_xor_sync(0xffffffffu, s, off);
        ss += __shfl_xor_sync(0xffffffffu, ss, off);
    }
    float mean = s * (1.f / Ww);
    float var  = ss * (1.f / Ww) - mean * mean;
    float rstd = rsqrtf(var + 1e-5f);
    #pragma unroll
    for (int i = 0; i < 8; i++) {
        int c4 = (i * 32 + lane) * 4;
        float4 gv = *(const float4*)(g + c4);
        float4 bv = *(const float4*)(beta + c4);
        float o0 = (v[i].x - mean) * rstd * gv.x + bv.x;
        float o1 = (v[i].y - mean) * rstd * gv.y + bv.y;
        float o2 = (v[i].z - mean) * rstd * gv.z + bv.z;
        float o3 = (v[i].w - mean) * rstd * gv.w + bv.w;
        uint2 o = make_uint2(pack_h2(o0, o1), pack_h2(o2, o3));
        *(uint2*)(yh + (size_t)row * Ww + c4) = o;
    }
}

// ----------------------------------------------------------------------------
// Tensor-core flash attention, fp16; exp2 softmax, deferred l reduction,
// K/V fragment double-buffering.
// ----------------------------------------------------------------------------
#define F_Q  0
#define F_ST 16384
#define F_K  0
#define F_V  8192
#define F_STAGE 16384
#define F_TOTAL (F_ST + 3 * F_STAGE)   // 64 KB

__global__ void __launch_bounds__(256, 2)
flash_tc(const __half* __restrict__ qh, __half* __restrict__ oh) {
    extern __shared__ char smem[];
    uint32_t sbm = smem_u32(smem);
    const int tid = threadIdx.x, wid = tid >> 5, lid = tid & 31;
    const int qt = blockIdx.x, h = blockIdx.y, b = blockIdx.z;
    const int wm = wid * 16;

    const size_t hcol = (size_t)h * 192;

    #pragma unroll
    for (int i = 0; i < 4; i++) {
        int idx = i * 256 + tid;
        int r = idx >> 3, c = (idx & 7) * 16;
        uint32_t so = SWZ128(r * 128 + c);
        const char* gq = (const char*)(qh + (size_t)(b * Nn + qt * 128 + r) * (3 * Ww) + hcol) + c;
        cp16(sbm + F_Q + so, gq);
    }
    CP_COMMIT();

    #define F_LOAD(kt, s) do { \
        uint32_t _dst = sbm + F_ST + (s) * F_STAGE; \
        _Pragma("unroll") \
        for (int _i = 0; _i < 2; _i++) { \
            int _idx = _i * 256 + tid; \
            int _r = _idx >> 3, _c = (_idx & 7) * 16; \
            uint32_t _so = SWZ128(_r * 128 + _c); \
            size_t _row = (size_t)(b * Nn + (kt) * 64 + _r) * (3 * Ww) + hcol; \
            cp16(_dst + F_K + _so, (const char*)(qh + _row + 64) + _c); \
            cp16(_dst + F_V + _so, (const char*)(qh + _row + 128) + _c); \
        } \
        CP_COMMIT(); \
    } while (0)

    F_LOAD(0, 0);
    F_LOAD(1, 1);

    const int a_r  = lid & 15;
    const int a_kb = (lid >> 4) * 16;
    const int k_row = ((lid >> 4) & 1) * 8 + (lid & 7);
    const int k_kb  = ((lid >> 3) & 1) * 16;
    const int v_row = ((lid >> 3) & 1) * 8 + (lid & 7);
    const int v_cb  = ((lid >> 4) & 1) * 16;

    float O[8][4];
    #pragma unroll
    for (int j = 0; j < 8; j++)
        #pragma unroll
        for (int r = 0; r < 4; r++) O[j][r] = 0.f;
    float m0 = -INFINITY, m1 = -INFINITY, l0 = 0.f, l1 = 0.f;

    const int NKT = Nn / 64;
    for (int kt = 0; kt < NKT; kt++) {
        if (kt + 1 < NKT) CP_WAIT1();
        else CP_WAIT0();
        __syncthreads();
        if (kt + 2 < NKT) F_LOAD(kt + 2, (kt + 2) % 3);
        uint32_t stg = sbm + F_ST + (kt % 3) * F_STAGE;

        float S[8][4];
        #pragma unroll
        for (int j = 0; j < 8; j++)
            #pragma unroll
            for (int r = 0; r < 4; r++) S[j][r] = 0.f;
        #pragma unroll
        for (int ks = 0; ks < 4; ks++) {
            uint32_t a0, a1, a2, a3;
            ldsm_x4(a0, a1, a2, a3, sbm + F_Q + SWZ128((wm + a_r) * 128 + ks * 32 + a_kb));
            uint32_t bk[2][4];
            ldsm_x4(bk[0][0], bk[0][1], bk[0][2], bk[0][3],
                    stg + F_K + SWZ128((k_row) * 128 + ks * 32 + k_kb));
            #pragma unroll
            for (int jp = 0; jp < 4; jp++) {
                const int cur = jp & 1;
                if (jp < 3)
                    ldsm_x4(bk[cur ^ 1][0], bk[cur ^ 1][1], bk[cur ^ 1][2], bk[cur ^ 1][3],
                            stg + F_K + SWZ128(((jp + 1) * 16 + k_row) * 128 + ks * 32 + k_kb));
                mma_f16(S[2 * jp + 0], a0, a1, a2, a3, bk[cur][0], bk[cur][1]);
                mma_f16(S[2 * jp + 1], a0, a1, a2, a3, bk[cur][2], bk[cur][3]);
            }
        }

        float mx0 = -INFINITY, mx1 = -INFINITY;
        #pragma unroll
        for (int j = 0; j < 8; j++) {
            mx0 = fmaxf(mx0, fmaxf(S[j][0], S[j][1]));
            mx1 = fmaxf(mx1, fmaxf(S[j][2], S[j][3]));
        }
        mx0 = fmaxf(mx0, __shfl_xor_sync(0xffffffffu, mx0, 1));
        mx0 = fmaxf(mx0, __shfl_xor_sync(0xffffffffu, mx0, 2));
        mx1 = fmaxf(mx1, __shfl_xor_sync(0xffffffffu, mx1, 1));
        mx1 = fmaxf(mx1, __shfl_xor_sync(0xffffffffu, mx1, 2));
        float nm0 = fmaxf(m0, mx0), nm1 = fmaxf(m1, mx1);
        float al0 = exp2f(m0 - nm0), al1 = exp2f(m1 - nm1);
        m0 = nm0; m1 = nm1;

        uint32_t P[8][2];
        float pl0 = 0.f, pl1 = 0.f;
        #pragma unroll
        for (int j = 0; j < 8; j++) {
            float e0 = exp2f(S[j][0] - nm0);
            float e1 = exp2f(S[j][1] - nm0);
            float e2 = exp2f(S[j][2] - nm1);
            float e3 = exp2f(S[j][3] - nm1);
            pl0 += e0 + e1;
            pl1 += e2 + e3;
            P[j][0] = pack_h2(e0, e1);
            P[j][1] = pack_h2(e2, e3);
        }
        l0 = l0 * al0 + pl0;
        l1 = l1 * al1 + pl1;

        if (!__all_sync(0xffffffffu, (al0 == 1.f) & (al1 == 1.f))) {
            #pragma unroll
            for (int j = 0; j < 8; j++) {
                O[j][0] *= al0; O[j][1] *= al0;
                O[j][2] *= al1; O[j][3] *= al1;
            }
        }

        #pragma unroll
        for (int t = 0; t < 4; t++) {
            uint32_t ph0 = P[2 * t][0], ph1 = P[2 * t][1];
            uint32_t ph2 = P[2 * t + 1][0], ph3 = P[2 * t + 1][1];
            uint32_t vv[2][4];
            ldsm_x4t(vv[0][0], vv[0][1], vv[0][2], vv[0][3],
                     stg + F_V + SWZ128((t * 16 + v_row) * 128 + v_cb));
            #pragma unroll
            for (int jp = 0; jp < 4; jp++) {
                const int cur = jp & 1;
                if (jp < 3)
                    ldsm_x4t(vv[cur ^ 1][0], vv[cur ^ 1][1], vv[cur ^ 1][2], vv[cur ^ 1][3],
                             stg + F_V + SWZ128((t * 16 + v_row) * 128 + (jp + 1) * 32 + v_cb));
                mma_f16(O[2 * jp + 0], ph0, ph1, ph2, ph3, vv[cur][0], vv[cur][1]);
                mma_f16(O[2 * jp + 1], ph0, ph1, ph2, ph3, vv[cur][2], vv[cur][3]);
            }
        }
    }
    #undef F_LOAD

    l0 += __shfl_xor_sync(0xffffffffu, l0, 1);
    l0 += __shfl_xor_sync(0xffffffffu, l0, 2);
    l1 += __shfl_xor_sync(0xffffffffu, l1, 1);
    l1 += __shfl_xor_sync(0xffffffffu, l1, 2);

    float inv0 = 1.f / l0, inv1 = 1.f / l1;
    int r0 = b * Nn + qt * 128 + wm + (lid >> 2);
    int r1 = r0 + 8;
    int cb = h * 64 + (lid & 3) * 2;
    #pragma unroll
    for (int j = 0; j < 8; j++) {
        int col = cb + j * 8;
        *(uint32_t*)(oh + (size_t)r0 * Ww + col) = pack_h2(O[j][0] * inv0, O[j][1] * inv0);
        *(uint32_t*)(oh + (size_t)r1 * Ww + col) = pack_h2(O[j][2] * inv1, O[j][3] * inv1);
    }
}

// ----------------------------------------------------------------------------
// Launcher
// ----------------------------------------------------------------------------
extern "C" void kernel_launch(void* const* d_in, const int* in_sizes, int n_in,
                              void* d_out, int out_size) {
    const float* x      = (const float*)d_in[0];
    const float* ln1_g  = (const float*)d_in[1];
    const float* ln1_b  = (const float*)d_in[2];
    const float* qkv_w  = (const float*)d_in[3];
    const float* qkv_b  = (const float*)d_in[4];
    const float* proj_w = (const float*)d_in[5];
    const float* proj_b = (const float*)d_in[6];
    const float* ln2_g  = (const float*)d_in[7];
    const float* ln2_b  = (const float*)d_in[8];
    const float* fc_w   = (const float*)d_in[9];
    const float* fc_b   = (const float*)d_in[10];
    const float* fc2_w  = (const float*)d_in[11];
    const float* fc2_b  = (const float*)d_in[12];
    float* out = (float*)d_out;

    float* x1;
    __half *ah, *qh, *ath, *hh, *w0, *w1, *w2, *w3;
    cudaGetSymbolAddress((void**)&x1,  g_x1);
    cudaGetSymbolAddress((void**)&ah,  g_ah);
    cudaGetSymbolAddress((void**)&qh,  g_qh);
    cudaGetSymbolAddress((void**)&ath, g_ath);
    cudaGetSymbolAddress((void**)&hh,  g_hh);
    cudaGetSymbolAddress((void**)&w0,  g_w0);
    cudaGetSymbolAddress((void**)&w1,  g_w1);
    cudaGetSymbolAddress((void**)&w2,  g_w2);
    cudaGetSymbolAddress((void**)&w3,  g_w3);

    cudaFuncSetAttribute(tc_gemm<2>, cudaFuncAttributeMaxDynamicSharedMemorySize, GS_TOTAL);
    cudaFuncSetAttribute(tc_gemm<3>, cudaFuncAttributeMaxDynamicSharedMemorySize, GS_TOTAL);
    cudaFuncSetAttribute(tc_gemm<4>, cudaFuncAttributeMaxDynamicSharedMemorySize, GS_TOTAL);
    cudaFuncSetAttribute(flash_tc, cudaFuncAttributeMaxDynamicSharedMemorySize, F_TOTAL);

    convAll_kernel<<<12288, dim3(32, 8)>>>(qkv_w, proj_w, fc_w, fc2_w, w0, w1, w2, w3);

    ln_kernel<<<ROWS / 8, 256>>>(x, ln1_g, ln1_b, ah);
    tc_gemm<3><<<dim3(3 * Ww / 128, ROWS / 128), 256, GS_TOTAL>>>(
        ah, w0, qkv_b, nullptr, nullptr, qh, ROWS, 3 * Ww, Ww);
    flash_tc<<<dim3(Nn / 128, Hh, Bb), 256, F_TOTAL>>>(qh, ath);
    tc_gemm<2><<<dim3(Ww / 128, ROWS / 128), 256, GS_TOTAL>>>(
        ath, w1, proj_b, x, x1, nullptr, ROWS, Ww, Ww);
    ln_kernel<<<ROWS / 8, 256>>>(x1, ln2_g, ln2_b, ah);
    tc_gemm<4><<<dim3(4 * Ww / 128, ROWS / 128), 256, GS_TOTAL>>>(
        ah, w2, fc_b, nullptr, nullptr, hh, ROWS, 4 * Ww, Ww);
    tc_gemm<2><<<dim3(Ww / 128, ROWS / 128), 256, GS_TOTAL>>>(
        hh, w3, fc2_b, x1, out, nullptr, ROWS, Ww, 4 * Ww);
}

// round 17
// speedup vs baseline: 1.1038x; 1.0290x over previous
#include <cuda_runtime.h>
#include <cuda_fp16.h>
#include <math.h>
#include <stdint.h>

// Problem constants
#define Bb 2
#define Nn 2048
#define Ww 1024
#define Hh 16
#define HDd 64
#define ROWS (Bb * Nn)   // 4096

// ----------------------------------------------------------------------------
// Scratch buffers
// ----------------------------------------------------------------------------
__device__ float g_x1[ROWS * Ww];            // post-attention residual (fp32)
__device__ __half g_ah[ROWS * Ww];           // ln output (fp16)
__device__ __half g_qh[ROWS * 3 * Ww];       // qkv (q pre-scaled by 0.125*log2e), fp16
__device__ __half g_ath[ROWS * Ww];          // attention out (fp16)
__device__ __half g_hh[ROWS * 4 * Ww];       // gelu out (fp16)
// converted weights, [N,K] transposed fp16
__device__ __half g_w0[Ww * 3 * Ww];         // qkv_w^T
__device__ __half g_w1[Ww * Ww];             // proj_w^T
__device__ __half g_w2[Ww * 4 * Ww];         // fc_w^T
__device__ __half g_w3[4 * Ww * Ww];         // fc2_w^T

#define SWZ128(off) ((off) ^ (((off) >> 3) & 0x70))

__device__ __forceinline__ uint32_t smem_u32(const void* p) {
    uint32_t a;
    asm("{ .reg .u64 t; cvta.to.shared.u64 t, %1; cvt.u32.u64 %0, t; }" : "=r"(a) : "l"(p));
    return a;
}
__device__ __forceinline__ void cp16(uint32_t saddr, const void* g) {
    asm volatile("cp.async.cg.shared.global [%0], [%1], 16;" :: "r"(saddr), "l"(g));
}
#define CP_COMMIT() asm volatile("cp.async.commit_group;" ::: "memory")
#define CP_WAIT1()  asm volatile("cp.async.wait_group 1;" ::: "memory")
#define CP_WAIT0()  asm volatile("cp.async.wait_group 0;" ::: "memory")

__device__ __forceinline__ void ldsm_x4(uint32_t& a0, uint32_t& a1, uint32_t& a2, uint32_t& a3,
                                        uint32_t addr) {
    asm volatile("ldmatrix.sync.aligned.m8n8.x4.shared.b16 {%0,%1,%2,%3}, [%4];"
                 : "=r"(a0), "=r"(a1), "=r"(a2), "=r"(a3) : "r"(addr));
}
__device__ __forceinline__ void ldsm_x4t(uint32_t& a0, uint32_t& a1, uint32_t& a2, uint32_t& a3,
                                         uint32_t addr) {
    asm volatile("ldmatrix.sync.aligned.m8n8.x4.trans.shared.b16 {%0,%1,%2,%3}, [%4];"
                 : "=r"(a0), "=r"(a1), "=r"(a2), "=r"(a3) : "r"(addr));
}
__device__ __forceinline__ void mma_f16(float* c,
                                        uint32_t a0, uint32_t a1, uint32_t a2, uint32_t a3,
                                        uint32_t b0, uint32_t b1) {
    asm volatile(
        "mma.sync.aligned.m16n8k16.row.col.f32.f16.f16.f32 "
        "{%0,%1,%2,%3}, {%4,%5,%6,%7}, {%8,%9}, {%0,%1,%2,%3};"
        : "+f"(c[0]), "+f"(c[1]), "+f"(c[2]), "+f"(c[3])
        : "r"(a0), "r"(a1), "r"(a2), "r"(a3), "r"(b0), "r"(b1));
}
__device__ __forceinline__ uint32_t pack_h2(float a, float b) {
    __half2 t = __floats2half2_rn(a, b);
    return *(uint32_t*)&t;
}
// tanh-form GELU via single EX2 + fast reciprocal
__device__ __forceinline__ float gelu_fast(float x) {
    float x2 = x * x;
    float u = fmaf(0.044715f * x2, x, x);
    float z = exp2f(2.3021183f * u);
    return x * __fdividef(z, z + 1.0f);
}

// ----------------------------------------------------------------------------
// convAll: convert+transpose all 4 weights in ONE launch; vectorized stores.
// ----------------------------------------------------------------------------
__global__ void convAll_kernel(const float* __restrict__ w0, const float* __restrict__ w1,
                               const float* __restrict__ w2, const float* __restrict__ w3,
                               __half* __restrict__ d0, __half* __restrict__ d1,
                               __half* __restrict__ d2, __half* __restrict__ d3) {
    __shared__ float t[32][33];
    int id = blockIdx.x;
    const float* w; __half* d; int K, N;
    if (id < 3072)      { w = w0; d = d0; K = Ww;     N = 3 * Ww; }
    else if (id < 4096) { w = w1; d = d1; K = Ww;     N = Ww;     id -= 3072; }
    else if (id < 8192) { w = w2; d = d2; K = Ww;     N = 4 * Ww; id -= 4096; }
    else                { w = w3; d = d3; K = 4 * Ww; N = Ww;     id -= 8192; }
    int nx = N >> 5;
    int n0 = (id % nx) * 32, k0 = (id / nx) * 32;
    int tid = threadIdx.y * 32 + threadIdx.x;  // 256 threads
    int tx = threadIdx.x, ty = threadIdx.y;    // 32 x 8
    #pragma unroll
    for (int i = 0; i < 32; i += 8)
        t[ty + i][tx] = w[(size_t)(k0 + ty + i) * N + n0 + tx];
    __syncthreads();
    int row = tid >> 3;
    int c4  = (tid & 7) * 4;
    __half h0 = __float2half(t[c4 + 0][row]);
    __half h1 = __float2half(t[c4 + 1][row]);
    __half h2 = __float2half(t[c4 + 2][row]);
    __half h3 = __float2half(t[c4 + 3][row]);
    uint2 o;
    __half2 p0 = __halves2half2(h0, h1), p1 = __halves2half2(h2, h3);
    o.x = *(uint32_t*)&p0;
    o.y = *(uint32_t*)&p1;
    *(uint2*)(d + (size_t)(n0 + row) * K + k0 + c4) = o;
}

// ----------------------------------------------------------------------------
// cp.async 3-stage mma.sync fp16 GEMM, single barrier per K chunk,
// ks-level fragment double-buffering.  (unchanged R15 winner)
// ----------------------------------------------------------------------------
#define GS_A 0
#define GS_B 16384
#define GS_STAGE 32768
#define GS_TOTAL (3 * GS_STAGE)   // 96 KB

template <int EPI>
__global__ void __launch_bounds__(256, 2)
tc_gemm(const __half* __restrict__ A, const __half* __restrict__ B,
        const float* __restrict__ bias, const float* __restrict__ res,
        float* __restrict__ Cf, __half* __restrict__ Ch,
        int M, int N, int K) {
    extern __shared__ char smem[];
    uint32_t sb = smem_u32(smem);
    const int tid = threadIdx.x, wid = tid >> 5, lid = tid & 31;
    const int bm = blockIdx.y * 128, bn = blockIdx.x * 128;
    const int wm = (wid & 1) * 64;
    const int wn = (wid >> 1) * 32;

    float acc[4][4][4];
    #pragma unroll
    for (int i = 0; i < 4; i++)
        #pragma unroll
        for (int j = 0; j < 4; j++)
            #pragma unroll
            for (int r = 0; r < 4; r++) acc[i][j][r] = 0.f;

    const int a_r  = lid & 15;
    const int a_kb = (lid >> 4) * 16;
    const int b_row = ((lid >> 4) & 1) * 8 + (lid & 7);
    const int b_kb  = ((lid >> 3) & 1) * 16;

    const int nchunk = K >> 6;
    #define G_LOAD(ck, s) do { \
        const int _k0 = (ck) << 6; \
        uint32_t _dst = sb + (s) * GS_STAGE; \
        _Pragma("unroll") \
        for (int _i = 0; _i < 4; _i++) { \
            int _idx = _i * 256 + tid; \
            int _r = _idx >> 3, _c = (_idx & 7) * 16; \
            uint32_t _so = SWZ128(_r * 128 + _c); \
            cp16(_dst + GS_A + _so, (const char*)(A + (size_t)(bm + _r) * K + _k0) + _c); \
            cp16(_dst + GS_B + _so, (const char*)(B + (size_t)(bn + _r) * K + _k0) + _c); \
        } \
        CP_COMMIT(); \
    } while (0)

    uint32_t af[2][4][4], bf[2][2][4];
    #define LD_FRAG(ks, buf) do { \
        _Pragma("unroll") \
        for (int _i = 0; _i < 4; _i++) \
            ldsm_x4(af[buf][_i][0], af[buf][_i][1], af[buf][_i][2], af[buf][_i][3], \
                    stg + GS_A + SWZ128((wm + _i * 16 + a_r) * 128 + (ks) * 32 + a_kb)); \
        _Pragma("unroll") \
        for (int _jp = 0; _jp < 2; _jp++) \
            ldsm_x4(bf[buf][_jp][0], bf[buf][_jp][1], bf[buf][_jp][2], bf[buf][_jp][3], \
                    stg + GS_B + SWZ128((wn + _jp * 16 + b_row) * 128 + (ks) * 32 + b_kb)); \
    } while (0)

    G_LOAD(0, 0);
    G_LOAD(1, 1);
    for (int ck = 0; ck < nchunk; ck++) {
        if (ck + 1 < nchunk) CP_WAIT1();
        else CP_WAIT0();
        __syncthreads();
        if (ck + 2 < nchunk) G_LOAD(ck + 2, (ck + 2) % 3);
        uint32_t stg = sb + (ck % 3) * GS_STAGE;
        LD_FRAG(0, 0);
        #pragma unroll
        for (int ks = 0; ks < 4; ks++) {
            const int cur = ks & 1;
            if (ks < 3) LD_FRAG(ks + 1, cur ^ 1);
            #pragma unroll
            for (int jp = 0; jp < 2; jp++) {
                #pragma unroll
                for (int i = 0; i < 4; i++) {
                    mma_f16(acc[i][2 * jp + 0], af[cur][i][0], af[cur][i][1],
                            af[cur][i][2], af[cur][i][3], bf[cur][jp][0], bf[cur][jp][1]);
                    mma_f16(acc[i][2 * jp + 1], af[cur][i][0], af[cur][i][1],
                            af[cur][i][2], af[cur][i][3], bf[cur][jp][2], bf[cur][jp][3]);
                }
            }
        }
    }
    #undef LD_FRAG
    #undef G_LOAD

    const int er = lid >> 2;
    const int ec = (lid & 3) * 2;
    #pragma unroll
    for (int i = 0; i < 4; i++) {
        #pragma unroll
        for (int j = 0; j < 4; j++) {
            int col = bn + wn + j * 8 + ec;
            float2 bi = *(const float2*)(bias + col);
            #pragma unroll
            for (int half = 0; half < 2; half++) {
                int row = bm + wm + i * 16 + er + half * 8;
                float ox = acc[i][j][half * 2 + 0] + bi.x;
                float oy = acc[i][j][half * 2 + 1] + bi.y;
                if (EPI == 2) {
                    float2 rv = *(const float2*)(res + (size_t)row * N + col);
                    float2 o = make_float2(ox + rv.x, oy + rv.y);
                    *(float2*)(Cf + (size_t)row * N + col) = o;
                } else {
                    if (EPI == 3) {
                        float s = ((col % 192) < 64) ? 0.18033688f : 1.0f;
                        ox *= s; oy *= s;
                    }
                    if (EPI == 4) { ox = gelu_fast(ox); oy = gelu_fast(oy); }
                    *(uint32_t*)(Ch + (size_t)row * N + col) = pack_h2(ox, oy);
                }
            }
        }
    }
}

// ----------------------------------------------------------------------------
// LayerNorm -> fp16, one warp per row (8 rows / 256-thread block)
// ----------------------------------------------------------------------------
__global__ void ln_kernel(const float* __restrict__ x, const float* __restrict__ g,
                          const float* __restrict__ beta, __half* __restrict__ yh) {
    int row = blockIdx.x * 8 + (threadIdx.x >> 5);
    int lane = threadIdx.x & 31;
    const float* xr = x + (size_t)row * Ww;
    float4 v[8];
    float s = 0.f, ss = 0.f;
    #pragma unroll
    for (int i = 0; i < 8; i++) {
        v[i] = *(const float4*)(xr + (i * 32 + lane) * 4);
        s  += v[i].x + v[i].y + v[i].z + v[i].w;
        ss += v[i].x * v[i].x + v[i].y * v[i].y + v[i].z * v[i].z + v[i].w * v[i].w;
    }
    #pragma unroll
    for (int off = 16; off; off >>= 1) {
        s  += __shfl_xor_sync(0xffffffffu, s, off);
        ss += __shfl_xor_sync(0xffffffffu, ss, off);
    }
    float mean = s * (1.f / Ww);
    float var  = ss * (1.f / Ww) - mean * mean;
    float rstd = rsqrtf(var + 1e-5f);
    #pragma unroll
    for (int i = 0; i < 8; i++) {
        int c4 = (i * 32 + lane) * 4;
        float4 gv = *(const float4*)(g + c4);
        float4 bv = *(const float4*)(beta + c4);
        float o0 = (v[i].x - mean) * rstd * gv.x + bv.x;
        float o1 = (v[i].y - mean) * rstd * gv.y + bv.y;
        float o2 = (v[i].z - mean) * rstd * gv.z + bv.z;
        float o3 = (v[i].w - mean) * rstd * gv.w + bv.w;
        uint2 o = make_uint2(pack_h2(o0, o1), pack_h2(o2, o3));
        *(uint2*)(yh + (size_t)row * Ww + c4) = o;
    }
}

// ----------------------------------------------------------------------------
// Tensor-core flash attention, fp16; 4-warp CTA (64 queries), 4 CTA/SM.
// exp2 softmax, deferred l reduction.
// ----------------------------------------------------------------------------
#define F_Q  0
#define F_ST 8192
#define F_K  0
#define F_V  8192
#define F_STAGE 16384
#define F_TOTAL (F_ST + 3 * F_STAGE)   // 56 KB

__global__ void __launch_bounds__(128, 4)
flash_tc(const __half* __restrict__ qh, __half* __restrict__ oh) {
    extern __shared__ char smem[];
    uint32_t sbm = smem_u32(smem);
    const int tid = threadIdx.x, wid = tid >> 5, lid = tid & 31;
    const int qt = blockIdx.x, h = blockIdx.y, b = blockIdx.z;
    const int wm = wid * 16;

    const size_t hcol = (size_t)h * 192;

    // Q: 64 rows x 128B = 8KB, 128 threads -> 4 cp16 each
    #pragma unroll
    for (int i = 0; i < 4; i++) {
        int idx = i * 128 + tid;
        int r = idx >> 3, c = (idx & 7) * 16;
        uint32_t so = SWZ128(r * 128 + c);
        const char* gq = (const char*)(qh + (size_t)(b * Nn + qt * 64 + r) * (3 * Ww) + hcol) + c;
        cp16(sbm + F_Q + so, gq);
    }
    CP_COMMIT();

    #define F_LOAD(kt, s) do { \
        uint32_t _dst = sbm + F_ST + (s) * F_STAGE; \
        _Pragma("unroll") \
        for (int _i = 0; _i < 4; _i++) { \
            int _idx = _i * 128 + tid; \
            int _r = _idx >> 3, _c = (_idx & 7) * 16; \
            uint32_t _so = SWZ128(_r * 128 + _c); \
            size_t _row = (size_t)(b * Nn + (kt) * 64 + _r) * (3 * Ww) + hcol; \
            cp16(_dst + F_K + _so, (const char*)(qh + _row + 64) + _c); \
            cp16(_dst + F_V + _so, (const char*)(qh + _row + 128) + _c); \
        } \
        CP_COMMIT(); \
    } while (0)

    F_LOAD(0, 0);
    F_LOAD(1, 1);

    const int a_r  = lid & 15;
    const int a_kb = (lid >> 4) * 16;
    const int k_row = ((lid >> 4) & 1) * 8 + (lid & 7);
    const int k_kb  = ((lid >> 3) & 1) * 16;
    const int v_row = ((lid >> 3) & 1) * 8 + (lid & 7);
    const int v_cb  = ((lid >> 4) & 1) * 16;

    float O[8][4];
    #pragma unroll
    for (int j = 0; j < 8; j++)
        #pragma unroll
        for (int r = 0; r < 4; r++) O[j][r] = 0.f;
    float m0 = -INFINITY, m1 = -INFINITY, l0 = 0.f, l1 = 0.f;

    const int NKT = Nn / 64;
    for (int kt = 0; kt < NKT; kt++) {
        if (kt + 1 < NKT) CP_WAIT1();
        else CP_WAIT0();
        __syncthreads();
        if (kt + 2 < NKT) F_LOAD(kt + 2, (kt + 2) % 3);
        uint32_t stg = sbm + F_ST + (kt % 3) * F_STAGE;

        float S[8][4];
        #pragma unroll
        for (int j = 0; j < 8; j++)
            #pragma unroll
            for (int r = 0; r < 4; r++) S[j][r] = 0.f;
        #pragma unroll
        for (int ks = 0; ks < 4; ks++) {
            uint32_t a0, a1, a2, a3;
            ldsm_x4(a0, a1, a2, a3, sbm + F_Q + SWZ128((wm + a_r) * 128 + ks * 32 + a_kb));
            #pragma unroll
            for (int jp = 0; jp < 4; jp++) {
                uint32_t b0, b1, b2, b3;
                uint32_t off = SWZ128((jp * 16 + k_row) * 128 + ks * 32 + k_kb);
                ldsm_x4(b0, b1, b2, b3, stg + F_K + off);
                mma_f16(S[2 * jp + 0], a0, a1, a2, a3, b0, b1);
                mma_f16(S[2 * jp + 1], a0, a1, a2, a3, b2, b3);
            }
        }

        float mx0 = -INFINITY, mx1 = -INFINITY;
        #pragma unroll
        for (int j = 0; j < 8; j++) {
            mx0 = fmaxf(mx0, fmaxf(S[j][0], S[j][1]));
            mx1 = fmaxf(mx1, fmaxf(S[j][2], S[j][3]));
        }
        mx0 = fmaxf(mx0, __shfl_xor_sync(0xffffffffu, mx0, 1));
        mx0 = fmaxf(mx0, __shfl_xor_sync(0xffffffffu, mx0, 2));
        mx1 = fmaxf(mx1, __shfl_xor_sync(0xffffffffu, mx1, 1));
        mx1 = fmaxf(mx1, __shfl_xor_sync(0xffffffffu, mx1, 2));
        float nm0 = fmaxf(m0, mx0), nm1 = fmaxf(m1, mx1);
        float al0 = exp2f(m0 - nm0), al1 = exp2f(m1 - nm1);
        m0 = nm0; m1 = nm1;

        uint32_t P[8][2];
        float pl0 = 0.f, pl1 = 0.f;
        #pragma unroll
        for (int j = 0; j < 8; j++) {
            float e0 = exp2f(S[j][0] - nm0);
            float e1 = exp2f(S[j][1] - nm0);
            float e2 = exp2f(S[j][2] - nm1);
            float e3 = exp2f(S[j][3] - nm1);
            pl0 += e0 + e1;
            pl1 += e2 + e3;
            P[j][0] = pack_h2(e0, e1);
            P[j][1] = pack_h2(e2, e3);
        }
        l0 = l0 * al0 + pl0;
        l1 = l1 * al1 + pl1;

        if (!__all_sync(0xffffffffu, (al0 == 1.f) & (al1 == 1.f))) {
            #pragma unroll
            for (int j = 0; j < 8; j++) {
                O[j][0] *= al0; O[j][1] *= al0;
                O[j][2] *= al1; O[j][3] *= al1;
            }
        }

        #pragma unroll
        for (int t = 0; t < 4; t++) {
            uint32_t ph0 = P[2 * t][0], ph1 = P[2 * t][1];
            uint32_t ph2 = P[2 * t + 1][0], ph3 = P[2 * t + 1][1];
            #pragma unroll
            for (int jp = 0; jp < 4; jp++) {
                uint32_t v0, v1, v2, v3;
                uint32_t off = SWZ128((t * 16 + v_row) * 128 + jp * 32 + v_cb);
                ldsm_x4t(v0, v1, v2, v3, stg + F_V + off);
                mma_f16(O[2 * jp + 0], ph0, ph1, ph2, ph3, v0, v1);
                mma_f16(O[2 * jp + 1], ph0, ph1, ph2, ph3, v2, v3);
            }
        }
    }
    #undef F_LOAD

    l0 += __shfl_xor_sync(0xffffffffu, l0, 1);
    l0 += __shfl_xor_sync(0xffffffffu, l0, 2);
    l1 += __shfl_xor_sync(0xffffffffu, l1, 1);
    l1 += __shfl_xor_sync(0xffffffffu, l1, 2);

    float inv0 = 1.f / l0, inv1 = 1.f / l1;
    int r0 = b * Nn + qt * 64 + wm + (lid >> 2);
    int r1 = r0 + 8;
    int cb = h * 64 + (lid & 3) * 2;
    #pragma unroll
    for (int j = 0; j < 8; j++) {
        int col = cb + j * 8;
        *(uint32_t*)(oh + (size_t)r0 * Ww + col) = pack_h2(O[j][0] * inv0, O[j][1] * inv0);
        *(uint32_t*)(oh + (size_t)r1 * Ww + col) = pack_h2(O[j][2] * inv1, O[j][3] * inv1);
    }
}

// ----------------------------------------------------------------------------
// Launcher
// ----------------------------------------------------------------------------
extern "C" void kernel_launch(void* const* d_in, const int* in_sizes, int n_in,
                              void* d_out, int out_size) {
    const float* x      = (const float*)d_in[0];
    const float* ln1_g  = (const float*)d_in[1];
    const float* ln1_b  = (const float*)d_in[2];
    const float* qkv_w  = (const float*)d_in[3];
    const float* qkv_b  = (const float*)d_in[4];
    const float* proj_w = (const float*)d_in[5];
    const float* proj_b = (const float*)d_in[6];
    const float* ln2_g  = (const float*)d_in[7];
    const float* ln2_b  = (const float*)d_in[8];
    const float* fc_w   = (const float*)d_in[9];
    const float* fc_b   = (const float*)d_in[10];
    const float* fc2_w  = (const float*)d_in[11];
    const float* fc2_b  = (const float*)d_in[12];
    float* out = (float*)d_out;

    float* x1;
    __half *ah, *qh, *ath, *hh, *w0, *w1, *w2, *w3;
    cudaGetSymbolAddress((void**)&x1,  g_x1);
    cudaGetSymbolAddress((void**)&ah,  g_ah);
    cudaGetSymbolAddress((void**)&qh,  g_qh);
    cudaGetSymbolAddress((void**)&ath, g_ath);
    cudaGetSymbolAddress((void**)&hh,  g_hh);
    cudaGetSymbolAddress((void**)&w0,  g_w0);
    cudaGetSymbolAddress((void**)&w1,  g_w1);
    cudaGetSymbolAddress((void**)&w2,  g_w2);
    cudaGetSymbolAddress((void**)&w3,  g_w3);

    cudaFuncSetAttribute(tc_gemm<2>, cudaFuncAttributeMaxDynamicSharedMemorySize, GS_TOTAL);
    cudaFuncSetAttribute(tc_gemm<3>, cudaFuncAttributeMaxDynamicSharedMemorySize, GS_TOTAL);
    cudaFuncSetAttribute(tc_gemm<4>, cudaFuncAttributeMaxDynamicSharedMemorySize, GS_TOTAL);
    cudaFuncSetAttribute(flash_tc, cudaFuncAttributeMaxDynamicSharedMemorySize, F_TOTAL);

    convAll_kernel<<<12288, dim3(32, 8)>>>(qkv_w, proj_w, fc_w, fc2_w, w0, w1, w2, w3);

    ln_kernel<<<ROWS / 8, 256>>>(x, ln1_g, ln1_b, ah);
    tc_gemm<3><<<dim3(3 * Ww / 128, ROWS / 128), 256, GS_TOTAL>>>(
        ah, w0, qkv_b, nullptr, nullptr, qh, ROWS, 3 * Ww, Ww);
    flash_tc<<<dim3(Nn / 64, Hh, Bb), 128, F_TOTAL>>>(qh, ath);
    tc_gemm<2><<<dim3(Ww / 128, ROWS / 128), 256, GS_TOTAL>>>(
        ath, w1, proj_b, x, x1, nullptr, ROWS, Ww, Ww);
    ln_kernel<<<ROWS / 8, 256>>>(x1, ln2_g, ln2_b, ah);
    tc_gemm<4><<<dim3(4 * Ww / 128, ROWS / 128), 256, GS_TOTAL>>>(
        ah, w2, fc_b, nullptr, nullptr, hh, ROWS, 4 * Ww, Ww);
    tc_gemm<2><<<dim3(Ww / 128, ROWS / 128), 256, GS_TOTAL>>>(
        hh, w3, fc2_b, x1, out, nullptr, ROWS, Ww, 4 * Ww);
}